// round 10
// baseline (speedup 1.0000x reference)
#include <cuda_runtime.h>
#include <cuda_fp16.h>
#include <cstdint>
#include <cmath>

// ---------------- problem constants ----------------
#define TOKS 4096
#define DMODEL 2048
#define DFF 8192
#define NHEADS 16
#define DKH 128
#define SEQ 2048
#define BATCH 2

// ---------------- scratch (device globals) ----------------
__device__ __align__(128) __half g_ln1[TOKS * DMODEL];
__device__ __align__(128) __half g_ln2[TOKS * DMODEL];
__device__ __align__(128) __half g_q[TOKS * DMODEL];
__device__ __align__(128) __half g_k[TOKS * DMODEL];
__device__ __align__(128) __half g_v[TOKS * DMODEL];
__device__ __align__(128) __half g_ctx[TOKS * DMODEL];
__device__ __align__(128) __half g_h[TOKS * DFF];
__device__ __align__(128) __half g_wqkv[DMODEL * 3 * DMODEL];
__device__ __align__(128) __half g_wo[DMODEL * DMODEL];
__device__ __align__(128) __half g_w1[DMODEL * DFF];
__device__ __align__(128) __half g_w2[DFF * DMODEL];
__device__ int g_flag[1];

// ---------------- helpers ----------------
__device__ __forceinline__ uint32_t smem_u32(const void* p) {
    uint32_t a;
    asm("{ .reg .u64 t; cvta.to.shared.u64 t, %1; cvt.u32.u64 %0, t; }"
        : "=r"(a) : "l"(p));
    return a;
}

#define CP16(dst, src) \
    asm volatile("cp.async.cg.shared.global [%0], [%1], 16;" \
                 :: "r"(dst), "l"(src) : "memory")
#define CP_COMMIT() asm volatile("cp.async.commit_group;" ::: "memory")
#define CP_WAIT1()  asm volatile("cp.async.wait_group 1;" ::: "memory")

#define LDSM_X4(r, addr) \
    asm volatile("ldmatrix.sync.aligned.m8n8.x4.shared.b16 {%0,%1,%2,%3}, [%4];" \
        : "=r"((r)[0]), "=r"((r)[1]), "=r"((r)[2]), "=r"((r)[3]) : "r"(addr))
#define LDSM_X4T(r, addr) \
    asm volatile("ldmatrix.sync.aligned.m8n8.x4.trans.shared.b16 {%0,%1,%2,%3}, [%4];" \
        : "=r"((r)[0]), "=r"((r)[1]), "=r"((r)[2]), "=r"((r)[3]) : "r"(addr))

__device__ __forceinline__ void mma16(float* c, const uint32_t* a, uint32_t b0, uint32_t b1) {
    asm volatile(
        "mma.sync.aligned.m16n8k16.row.col.f32.f16.f16.f32 "
        "{%0,%1,%2,%3},{%4,%5,%6,%7},{%8,%9},{%0,%1,%2,%3};"
        : "+f"(c[0]), "+f"(c[1]), "+f"(c[2]), "+f"(c[3])
        : "r"(a[0]), "r"(a[1]), "r"(a[2]), "r"(a[3]), "r"(b0), "r"(b1));
}

__device__ __forceinline__ uint32_t pack_h2(float x, float y) {
    __half2 t = __floats2half2_rn(x, y);
    return *(uint32_t*)&t;
}

// ---------------- fp32 -> fp16 converter (all 4 weights, one launch) ----------------
#define CVT_N0 (DMODEL * 3 * DMODEL / 4)
#define CVT_N1 (DMODEL * DMODEL / 4)
#define CVT_N2 (DMODEL * DFF / 4)
__global__ void cvt_all(const float* __restrict__ wqkv, const float* __restrict__ wo,
                        const float* __restrict__ w1, const float* __restrict__ w2,
                        __half* __restrict__ oqkv, __half* __restrict__ owo,
                        __half* __restrict__ ow1, __half* __restrict__ ow2) {
    int idx = blockIdx.x * blockDim.x + threadIdx.x;
    const float* in;
    __half* out;
    int off;
    if (idx < CVT_N0)                          { in = wqkv; out = oqkv; off = idx; }
    else if (idx < CVT_N0 + CVT_N1)            { in = wo;   out = owo;  off = idx - CVT_N0; }
    else if (idx < CVT_N0 + CVT_N1 + CVT_N2)   { in = w1;   out = ow1;  off = idx - CVT_N0 - CVT_N1; }
    else                                       { in = w2;   out = ow2;  off = idx - CVT_N0 - CVT_N1 - CVT_N2; }
    float4 v = ((const float4*)in)[off];
    ((__half2*)out)[off * 2]     = __floats2half2_rn(v.x, v.y);
    ((__half2*)out)[off * 2 + 1] = __floats2half2_rn(v.z, v.w);
}

// ---------------- LayerNorm: fp32 x -> fp16 ln1, ln2 ----------------
__global__ void ln_kernel(const float* __restrict__ x,
                          const float* __restrict__ ga1, const float* __restrict__ be1,
                          const float* __restrict__ ga2, const float* __restrict__ be2,
                          __half* __restrict__ o1, __half* __restrict__ o2) {
    int t = blockIdx.x;
    int tid = threadIdx.x;
    const float4* xr = (const float4*)(x + (size_t)t * DMODEL);
    float4 a = xr[tid];
    float4 bq = xr[tid + 256];
    float s  = a.x + a.y + a.z + a.w + bq.x + bq.y + bq.z + bq.w;
    float s2 = a.x*a.x + a.y*a.y + a.z*a.z + a.w*a.w +
               bq.x*bq.x + bq.y*bq.y + bq.z*bq.z + bq.w*bq.w;
    #pragma unroll
    for (int o = 16; o; o >>= 1) {
        s  += __shfl_xor_sync(0xffffffffu, s,  o);
        s2 += __shfl_xor_sync(0xffffffffu, s2, o);
    }
    __shared__ float rs[8], rs2[8], stats[2];
    if ((tid & 31) == 0) { rs[tid >> 5] = s; rs2[tid >> 5] = s2; }
    __syncthreads();
    if (tid == 0) {
        float S = 0.f, S2 = 0.f;
        for (int i = 0; i < 8; i++) { S += rs[i]; S2 += rs2[i]; }
        float mu = S * (1.0f / DMODEL);
        float var = S2 * (1.0f / DMODEL) - mu * mu;
        stats[0] = mu;
        stats[1] = rsqrtf(var + 1e-5f);
    }
    __syncthreads();
    float mu = stats[0], r = stats[1];
    const float4* G1 = (const float4*)ga1;
    const float4* B1 = (const float4*)be1;
    const float4* G2 = (const float4*)ga2;
    const float4* B2 = (const float4*)be2;
    __half2* O1 = (__half2*)(o1 + (size_t)t * DMODEL);
    __half2* O2 = (__half2*)(o2 + (size_t)t * DMODEL);
    #pragma unroll
    for (int i = 0; i < 2; i++) {
        int idx = tid + i * 256;
        float4 v = (i == 0) ? a : bq;
        float nx = (v.x - mu) * r, ny = (v.y - mu) * r, nz = (v.z - mu) * r, nw = (v.w - mu) * r;
        float4 g1v = G1[idx], b1v = B1[idx], g2v = G2[idx], b2v = B2[idx];
        O1[idx * 2]     = __floats2half2_rn(nx * g1v.x + b1v.x, ny * g1v.y + b1v.y);
        O1[idx * 2 + 1] = __floats2half2_rn(nz * g1v.z + b1v.z, nw * g1v.w + b1v.w);
        O2[idx * 2]     = __floats2half2_rn(nx * g2v.x + b2v.x, ny * g2v.y + b2v.y);
        O2[idx * 2 + 1] = __floats2half2_rn(nz * g2v.z + b2v.z, nw * g2v.w + b2v.w);
    }
}

// ---------------- mask flag ----------------
__global__ void flag_init(int* flag) { if (threadIdx.x == 0) flag[0] = 1; }

__global__ void mask_reduce(const int* __restrict__ mask, int n, int* __restrict__ flag) {
    bool bad = false;
    for (int i = blockIdx.x * blockDim.x + threadIdx.x; i < n; i += gridDim.x * blockDim.x)
        if (mask[i] == 0) bad = true;
    if (bad) flag[0] = 0;
}

// ======== fp16 GEMM: 128x256 tile, K-chunk 64, 3 stages, 256 threads ========
// 8 warps, warp tile 64x64, fragment double-buffering in registers.
#define A_ROWB  144                 // 64 halfs + 16B pad
#define A_BYTES (128 * A_ROWB)      // 18432
#define B_ROWB  528
#define STAGE   (A_BYTES + 64 * B_ROWB)   // 52224
#define NSTAGE  3
#define SMEM_GEMM (STAGE * NSTAGE)        // 156672

struct Epi {
    const float* c0;   // bias
    const float* c1;   // layer_scale
    const float* c2;   // x residual
    float* o0;         // fp32 out
    __half* bo0;
    __half* bo1;
    __half* bo2;
};

// E=0: QKV head split.  E=1: out += v (WO accumulate).
// E=2: h = gelu(v + b1). E=3: out = x + ls*(v + b2) (FF2 init).
template <int E>
__device__ __forceinline__ void emit2(int r, int c, int N, float v0, float v1, const Epi& e) {
    if (E == 0) {
        int which = c >> 11, hh = (c >> 7) & 15, d0 = c & 127;
        __half* dst = (which == 0) ? e.bo0 : ((which == 1) ? e.bo1 : e.bo2);
        int b = r >> 11, s = r & 2047;
        __half* p = dst + (size_t)((b << 4) + hh) * (SEQ * DKH) + (size_t)s * DKH + d0;
        *(__half2*)p = __floats2half2_rn(v0, v1);
    } else if (E == 1) {
        size_t i = (size_t)r * N + c;
        float2 o = *(const float2*)(e.o0 + i);
        o.x += v0;
        o.y += v1;
        *(float2*)(e.o0 + i) = o;
    } else if (E == 2) {
        const float is2 = 0.70710678118654752f;
        float t0 = v0 + e.c0[c], t1 = v1 + e.c0[c + 1];
        float g0 = 0.5f * t0 * (1.0f + erff(t0 * is2));
        float g1 = 0.5f * t1 * (1.0f + erff(t1 * is2));
        __half* p = e.bo0 + (size_t)r * N + c;
        *(__half2*)p = __floats2half2_rn(g0, g1);
    } else {
        size_t i = (size_t)r * N + c;
        float2 xv = *(const float2*)(e.c2 + i);
        float2 bb = *(const float2*)(e.c0 + c);
        float2 ls = *(const float2*)(e.c1 + c);
        float2 o;
        o.x = xv.x + ls.x * (v0 + bb.x);
        o.y = xv.y + ls.y * (v1 + bb.y);
        *(float2*)(e.o0 + i) = o;
    }
}

__device__ __forceinline__ void gemm_load_stage(const __half* A, const __half* B,
                                                int K, int N, int bm, int bn, int kt,
                                                uint32_t base, int tid) {
    // A: 128 rows x 64 halfs = 1024 16B-chunks (4 per thread)
    #pragma unroll
    for (int t = 0; t < 4; t++) {
        int c = tid + t * 256;
        int row = c >> 3, k8 = c & 7;
        const __half* src = A + (size_t)(bm + row) * K + kt * 64 + k8 * 8;
        CP16(base + (uint32_t)row * A_ROWB + (uint32_t)k8 * 16, src);
    }
    // B: 64 rows x 256 halfs = 2048 16B-chunks (8 per thread)
    #pragma unroll
    for (int t = 0; t < 8; t++) {
        int c = tid + t * 256;
        int row = c >> 5, n8 = c & 31;
        const __half* src = B + (size_t)(kt * 64 + row) * N + bn + n8 * 8;
        CP16(base + A_BYTES + (uint32_t)row * B_ROWB + (uint32_t)n8 * 16, src);
    }
    CP_COMMIT();
}

template <int E>
__global__ __launch_bounds__(256, 1)
void gemm_f16(const __half* __restrict__ A, const __half* __restrict__ B,
              int M, int N, int K, Epi e) {
    extern __shared__ __align__(128) char smc[];
    uint32_t smb = smem_u32(smc);
    int tid = threadIdx.x, warp = tid >> 5, lane = tid & 31;
    int bm = blockIdx.y * 128, bn = blockIdx.x * 256;
    int wm = (warp >> 2) * 64, wn = (warp & 3) * 64;
    const int nt = K >> 6;

    float acc[4][8][4];
    #pragma unroll
    for (int i = 0; i < 4; i++)
        #pragma unroll
        for (int j = 0; j < 8; j++)
            #pragma unroll
            for (int k = 0; k < 4; k++) acc[i][j][k] = 0.f;

    gemm_load_stage(A, B, K, N, bm, bn, 0, smb, tid);
    gemm_load_stage(A, B, K, N, bm, bn, 1, smb + STAGE, tid);

    int frow = (lane & 7) + ((lane >> 3) & 1) * 8;
    int hi = lane >> 4;

    uint32_t af[2][4][4], bf[2][4][4];

    for (int i = 0; i < nt; i++) {
        CP_WAIT1();
        __syncthreads();
        if (i + 2 < nt)
            gemm_load_stage(A, B, K, N, bm, bn, i + 2, smb + (uint32_t)((i + 2) % 3) * STAGE, tid);

        uint32_t abase = smb + (uint32_t)(i % 3) * STAGE;
        uint32_t bbase = abase + A_BYTES;

        // prefetch k16=0 fragments
        #pragma unroll
        for (int mt = 0; mt < 4; mt++)
            LDSM_X4(af[0][mt], abase + (uint32_t)(wm + mt * 16 + frow) * A_ROWB
                             + (uint32_t)hi * 16);
        #pragma unroll
        for (int n16 = 0; n16 < 4; n16++)
            LDSM_X4T(bf[0][n16], bbase + (uint32_t)frow * B_ROWB
                               + (uint32_t)(((wn + n16 * 16) >> 3) + hi) * 16);

        #pragma unroll
        for (int k16 = 0; k16 < 4; k16++) {
            int cur = k16 & 1, nxt = cur ^ 1;
            if (k16 < 3) {
                #pragma unroll
                for (int mt = 0; mt < 4; mt++)
                    LDSM_X4(af[nxt][mt], abase + (uint32_t)(wm + mt * 16 + frow) * A_ROWB
                                       + (uint32_t)((k16 + 1) * 2 + hi) * 16);
                #pragma unroll
                for (int n16 = 0; n16 < 4; n16++)
                    LDSM_X4T(bf[nxt][n16], bbase + (uint32_t)((k16 + 1) * 16 + frow) * B_ROWB
                                         + (uint32_t)(((wn + n16 * 16) >> 3) + hi) * 16);
            }
            #pragma unroll
            for (int mt = 0; mt < 4; mt++)
                #pragma unroll
                for (int n8 = 0; n8 < 8; n8++)
                    mma16(acc[mt][n8], af[cur][mt],
                          bf[cur][n8 >> 1][(n8 & 1) * 2], bf[cur][n8 >> 1][(n8 & 1) * 2 + 1]);
        }
    }

    int g = lane >> 2, tq = lane & 3;
    #pragma unroll
    for (int mt = 0; mt < 4; mt++) {
        int r0 = bm + wm + mt * 16 + g;
        #pragma unroll
        for (int n8 = 0; n8 < 8; n8++) {
            int c0 = bn + wn + n8 * 8 + tq * 2;
            emit2<E>(r0,     c0, N, acc[mt][n8][0], acc[mt][n8][1], e);
            emit2<E>(r0 + 8, c0, N, acc[mt][n8][2], acc[mt][n8][3], e);
        }
    }
}

// ======== flash attention: fp16 mma16 + ldmatrix, single fp16 P ========
#define AKV_ROWB 272
#define AKV_MATB 17408
#define ATTN_SMEM (AKV_MATB * 5)

__global__ __launch_bounds__(128, 2)
void attn_f16(const __half* __restrict__ Q, const __half* __restrict__ K,
              const __half* __restrict__ V, const int* __restrict__ mask,
              const int* __restrict__ flag, __half* __restrict__ ctx) {
    extern __shared__ __align__(128) char sma[];
    uint32_t smb = smem_u32(sma);
    int tid = threadIdx.x, warp = tid >> 5, lane = tid & 31;
    int g = lane >> 2, tq = lane & 3;
    int frow = (lane & 7) + ((lane >> 3) & 1) * 8;
    int hi = lane >> 4;
    int qt = blockIdx.x, bh = blockIdx.y;
    int b = bh >> 4, h = bh & 15;
    const __half* Qg = Q + (size_t)bh * SEQ * DKH + (size_t)(qt * 64) * DKH;
    const __half* Kg = K + (size_t)bh * SEQ * DKH;
    const __half* Vg = V + (size_t)bh * SEQ * DKH;
    int q0 = qt * 64 + warp * 16;
    int allv = flag[0];

    {
        int row = tid >> 1, c16b = (tid & 1) * 8;
        #pragma unroll
        for (int t = 0; t < 8; t++) {
            CP16(smb + (uint32_t)row * AKV_ROWB + (uint32_t)(c16b + t) * 16,
                 Qg + (size_t)row * DKH + (c16b + t) * 8);
        }
        #pragma unroll
        for (int t = 0; t < 8; t++) {
            CP16(smb + AKV_MATB + (uint32_t)row * AKV_ROWB + (uint32_t)(c16b + t) * 16,
                 Kg + (size_t)row * DKH + (c16b + t) * 8);
            CP16(smb + AKV_MATB + AKV_MATB + (uint32_t)row * AKV_ROWB + (uint32_t)(c16b + t) * 16,
                 Vg + (size_t)row * DKH + (c16b + t) * 8);
        }
        CP_COMMIT();
        #pragma unroll
        for (int t = 0; t < 8; t++) {
            CP16(smb + AKV_MATB * 3 + (uint32_t)row * AKV_ROWB + (uint32_t)(c16b + t) * 16,
                 Kg + (size_t)(64 + row) * DKH + (c16b + t) * 8);
            CP16(smb + AKV_MATB * 4 + (uint32_t)row * AKV_ROWB + (uint32_t)(c16b + t) * 16,
                 Vg + (size_t)(64 + row) * DKH + (c16b + t) * 8);
        }
        CP_COMMIT();
    }

    CP_WAIT1();
    __syncthreads();

    uint32_t qa[8][4];
    #pragma unroll
    for (int k16 = 0; k16 < 8; k16++)
        LDSM_X4(qa[k16], smb + (uint32_t)(warp * 16 + frow) * AKV_ROWB
                             + (uint32_t)(k16 * 2 + hi) * 16);

    float o[16][4];
    #pragma unroll
    for (int i = 0; i < 16; i++)
        #pragma unroll
        for (int j = 0; j < 4; j++) o[i][j] = 0.f;
    float mA = -1e30f, mB = -1e30f, lA = 0.f, lB = 0.f;

    for (int j = 0; j < 32; j++) {
        if (j > 0) { CP_WAIT1(); __syncthreads(); }
        int buf = j & 1;
        uint32_t kbase = smb + AKV_MATB + (uint32_t)buf * (2 * AKV_MATB);
        uint32_t vbase = kbase + AKV_MATB;

        float sc[8][4];
        #pragma unroll
        for (int ni = 0; ni < 8; ni++)
            #pragma unroll
            for (int c = 0; c < 4; c++) sc[ni][c] = 0.f;
        #pragma unroll
        for (int k16 = 0; k16 < 8; k16++) {
            #pragma unroll
            for (int n16 = 0; n16 < 4; n16++) {
                uint32_t kb[4];
                LDSM_X4(kb, kbase + (uint32_t)(n16 * 16 + frow) * AKV_ROWB
                                  + (uint32_t)(k16 * 2 + hi) * 16);
                mma16(sc[n16 * 2],     qa[k16], kb[0], kb[2]);
                mma16(sc[n16 * 2 + 1], qa[k16], kb[1], kb[3]);
            }
        }
        const float sscale = 0.0883883476483184f;
        #pragma unroll
        for (int ni = 0; ni < 8; ni++)
            #pragma unroll
            for (int c = 0; c < 4; c++) sc[ni][c] *= sscale;

        if (!allv) {
            #pragma unroll
            for (int ni = 0; ni < 8; ni++) {
                int kc = j * 64 + ni * 8 + tq * 2;
                int r0 = q0 + g, r1 = q0 + g + 8;
                if (mask[(size_t)r0 * SEQ + kc] == 0)     sc[ni][0] = -1e9f;
                if (mask[(size_t)r0 * SEQ + kc + 1] == 0) sc[ni][1] = -1e9f;
                if (mask[(size_t)r1 * SEQ + kc] == 0)     sc[ni][2] = -1e9f;
                if (mask[(size_t)r1 * SEQ + kc + 1] == 0) sc[ni][3] = -1e9f;
            }
        }

        float mxA = -1e30f, mxB = -1e30f;
        #pragma unroll
        for (int ni = 0; ni < 8; ni++) {
            mxA = fmaxf(mxA, fmaxf(sc[ni][0], sc[ni][1]));
            mxB = fmaxf(mxB, fmaxf(sc[ni][2], sc[ni][3]));
        }
        mxA = fmaxf(mxA, __shfl_xor_sync(0xffffffffu, mxA, 1));
        mxA = fmaxf(mxA, __shfl_xor_sync(0xffffffffu, mxA, 2));
        mxB = fmaxf(mxB, __shfl_xor_sync(0xffffffffu, mxB, 1));
        mxB = fmaxf(mxB, __shfl_xor_sync(0xffffffffu, mxB, 2));
        float mAn = fmaxf(mA, mxA), mBn = fmaxf(mB, mxB);
        float aA = __expf(mA - mAn), aB = __expf(mB - mBn);
        float sA = 0.f, sB = 0.f;
        #pragma unroll
        for (int ni = 0; ni < 8; ni++) {
            sc[ni][0] = __expf(sc[ni][0] - mAn); sA += sc[ni][0];
            sc[ni][1] = __expf(sc[ni][1] - mAn); sA += sc[ni][1];
            sc[ni][2] = __expf(sc[ni][2] - mBn); sB += sc[ni][2];
            sc[ni][3] = __expf(sc[ni][3] - mBn); sB += sc[ni][3];
        }
        sA += __shfl_xor_sync(0xffffffffu, sA, 1);
        sA += __shfl_xor_sync(0xffffffffu, sA, 2);
        sB += __shfl_xor_sync(0xffffffffu, sB, 1);
        sB += __shfl_xor_sync(0xffffffffu, sB, 2);
        lA = lA * aA + sA;
        lB = lB * aB + sB;
        mA = mAn; mB = mBn;
        #pragma unroll
        for (int ni = 0; ni < 16; ni++) {
            o[ni][0] *= aA; o[ni][1] *= aA;
            o[ni][2] *= aB; o[ni][3] *= aB;
        }

        uint32_t pa[4][4];
        #pragma unroll
        for (int jj = 0; jj < 4; jj++) {
            float* e0 = sc[2 * jj];
            float* e1 = sc[2 * jj + 1];
            pa[jj][0] = pack_h2(e0[0], e0[1]);
            pa[jj][1] = pack_h2(e0[2], e0[3]);
            pa[jj][2] = pack_h2(e1[0], e1[1]);
            pa[jj][3] = pack_h2(e1[2], e1[3]);
        }

        #pragma unroll
        for (int k16 = 0; k16 < 4; k16++) {
            #pragma unroll
            for (int n16 = 0; n16 < 8; n16++) {
                uint32_t vb4[4];
                LDSM_X4T(vb4, vbase + (uint32_t)(k16 * 16 + frow) * AKV_ROWB
                                    + (uint32_t)(n16 * 2 + hi) * 16);
                mma16(o[n16 * 2],     pa[k16], vb4[0], vb4[1]);
                mma16(o[n16 * 2 + 1], pa[k16], vb4[2], vb4[3]);
            }
        }

        __syncthreads();
        if (j + 2 < 32) {
            int row = tid >> 1, c16b = (tid & 1) * 8;
            uint32_t kd = smb + AKV_MATB + (uint32_t)buf * (2 * AKV_MATB);
            const __half* ks = Kg + (size_t)((j + 2) * 64 + row) * DKH;
            const __half* vs = Vg + (size_t)((j + 2) * 64 + row) * DKH;
            #pragma unroll
            for (int t = 0; t < 8; t++) {
                CP16(kd + (uint32_t)row * AKV_ROWB + (uint32_t)(c16b + t) * 16,
                     ks + (c16b + t) * 8);
                CP16(kd + AKV_MATB + (uint32_t)row * AKV_ROWB + (uint32_t)(c16b + t) * 16,
                     vs + (c16b + t) * 8);
            }
            CP_COMMIT();
        }
    }

    float rA = 1.f / lA, rB = 1.f / lB;
    int tok0 = b * SEQ + q0 + g, tok1 = tok0 + 8;
    #pragma unroll
    for (int ni = 0; ni < 16; ni++) {
        int d = ni * 8 + tq * 2;
        __half* p0 = ctx + (size_t)tok0 * DMODEL + h * DKH + d;
        __half* p1 = ctx + (size_t)tok1 * DMODEL + h * DKH + d;
        *(__half2*)p0 = __floats2half2_rn(o[ni][0] * rA, o[ni][1] * rA);
        *(__half2*)p1 = __floats2half2_rn(o[ni][2] * rB, o[ni][3] * rB);
    }
}

// ---------------- launch ----------------
extern "C" void kernel_launch(void* const* d_in, const int* in_sizes, int n_in,
                              void* d_out, int out_size) {
    const float* x     = (const float*)d_in[0];
    const int*   mask  = (const int*)d_in[1];
    const float* w_qkv = (const float*)d_in[2];
    const float* w_o   = (const float*)d_in[3];
    const float* ga1   = (const float*)d_in[4];
    const float* be1   = (const float*)d_in[5];
    const float* ga2   = (const float*)d_in[6];
    const float* be2   = (const float*)d_in[7];
    const float* w1    = (const float*)d_in[8];
    const float* b1    = (const float*)d_in[9];
    const float* w2    = (const float*)d_in[10];
    const float* b2    = (const float*)d_in[11];
    const float* ls    = (const float*)d_in[12];
    float* out = (float*)d_out;

    __half *ln1, *ln2, *q, *k, *v, *ctx, *hbuf, *wqkvb, *wob, *w1b, *w2b;
    int* flag;
    cudaGetSymbolAddress((void**)&ln1,   g_ln1);
    cudaGetSymbolAddress((void**)&ln2,   g_ln2);
    cudaGetSymbolAddress((void**)&q,     g_q);
    cudaGetSymbolAddress((void**)&k,     g_k);
    cudaGetSymbolAddress((void**)&v,     g_v);
    cudaGetSymbolAddress((void**)&ctx,   g_ctx);
    cudaGetSymbolAddress((void**)&hbuf,  g_h);
    cudaGetSymbolAddress((void**)&wqkvb, g_wqkv);
    cudaGetSymbolAddress((void**)&wob,   g_wo);
    cudaGetSymbolAddress((void**)&w1b,   g_w1);
    cudaGetSymbolAddress((void**)&w2b,   g_w2);
    cudaGetSymbolAddress((void**)&flag,  g_flag);

    cudaFuncSetAttribute(attn_f16, cudaFuncAttributeMaxDynamicSharedMemorySize, ATTN_SMEM);
    cudaFuncSetAttribute(gemm_f16<0>, cudaFuncAttributeMaxDynamicSharedMemorySize, SMEM_GEMM);
    cudaFuncSetAttribute(gemm_f16<1>, cudaFuncAttributeMaxDynamicSharedMemorySize, SMEM_GEMM);
    cudaFuncSetAttribute(gemm_f16<2>, cudaFuncAttributeMaxDynamicSharedMemorySize, SMEM_GEMM);
    cudaFuncSetAttribute(gemm_f16<3>, cudaFuncAttributeMaxDynamicSharedMemorySize, SMEM_GEMM);

    // side stream + events (host resources only; created once)
    static cudaStream_t s2 = nullptr;
    static cudaEvent_t evA = nullptr, evC = nullptr, evB = nullptr;
    if (s2 == nullptr) {
        cudaStreamCreateWithFlags(&s2, cudaStreamNonBlocking);
        cudaEventCreateWithFlags(&evA, cudaEventDisableTiming);
        cudaEventCreateWithFlags(&evC, cudaEventDisableTiming);
        cudaEventCreateWithFlags(&evB, cudaEventDisableTiming);
    }

    // ---- main stream: conversions + layernorm ----
    cvt_all<<<(CVT_N0 + CVT_N1 + 2 * CVT_N2) / 256, 256>>>(
        w_qkv, w_o, w1, w2, wqkvb, wob, w1b, w2b);
    ln_kernel<<<TOKS, 256>>>(x, ga1, be1, ga2, be2, ln1, ln2);
    cudaEventRecord(evA, 0);

    // ---- side stream: QKV projection ----
    cudaStreamWaitEvent(s2, evA, 0);
    Epi e1 = {nullptr, nullptr, nullptr, nullptr, q, k, v};
    gemm_f16<0><<<dim3(24, 32), 256, SMEM_GEMM, s2>>>(ln1, wqkvb, TOKS, 3 * DMODEL, DMODEL, e1);

    // ---- main: FF1 (ncu capture slot) ----
    Epi e3 = {b1, nullptr, nullptr, nullptr, hbuf, nullptr, nullptr};
    gemm_f16<2><<<dim3(32, 32), 256, SMEM_GEMM>>>(ln2, w1b, TOKS, DFF, DMODEL, e3);

    // ---- main: mask flag ----
    flag_init<<<1, 32>>>(flag);
    mask_reduce<<<256, 256>>>(mask, in_sizes[1], flag);
    cudaEventRecord(evC, 0);

    // ---- side: attention (needs QKV + mask flag) ----
    cudaStreamWaitEvent(s2, evC, 0);
    attn_f16<<<dim3(32, 32), 128, ATTN_SMEM, s2>>>(q, k, v, mask, flag, ctx);
    cudaEventRecord(evB, s2);

    // ---- main: FF2 initializes out = x + ls*(h@w2 + b2) ----
    Epi e4 = {b2, ls, x, out, nullptr, nullptr, nullptr};
    gemm_f16<3><<<dim3(8, 32), 256, SMEM_GEMM>>>(hbuf, w2b, TOKS, DMODEL, DFF, e4);

    // ---- join, then WO accumulates out += ctx @ w_o ----
    cudaStreamWaitEvent(0, evB, 0);
    Epi e2 = {nullptr, nullptr, nullptr, out, nullptr, nullptr, nullptr};
    gemm_f16<1><<<dim3(8, 32), 256, SMEM_GEMM>>>(ctx, wob, TOKS, DMODEL, DMODEL, e2);
}

// round 11
// speedup vs baseline: 1.0861x; 1.0861x over previous
#include <cuda_runtime.h>
#include <cuda_fp16.h>
#include <cstdint>
#include <cmath>

// ---------------- problem constants ----------------
#define TOKS 4096
#define DMODEL 2048
#define DFF 8192
#define NHEADS 16
#define DKH 128
#define SEQ 2048
#define BATCH 2

// ---------------- scratch (device globals) ----------------
__device__ __align__(128) __half g_ln1[TOKS * DMODEL];
__device__ __align__(128) __half g_ln2[TOKS * DMODEL];
__device__ __align__(128) __half g_q[TOKS * DMODEL];
__device__ __align__(128) __half g_k[TOKS * DMODEL];
__device__ __align__(128) __half g_v[TOKS * DMODEL];
__device__ __align__(128) __half g_ctx[TOKS * DMODEL];
__device__ __align__(128) __half g_h[TOKS * DFF];
__device__ __align__(128) __half g_wqkv[DMODEL * 3 * DMODEL];
__device__ __align__(128) __half g_wo[DMODEL * DMODEL];
__device__ __align__(128) __half g_w1[DMODEL * DFF];
__device__ __align__(128) __half g_w2[DFF * DMODEL];
__device__ int g_flag[1];

// ---------------- helpers ----------------
__device__ __forceinline__ uint32_t smem_u32(const void* p) {
    uint32_t a;
    asm("{ .reg .u64 t; cvta.to.shared.u64 t, %1; cvt.u32.u64 %0, t; }"
        : "=r"(a) : "l"(p));
    return a;
}

#define CP16(dst, src) \
    asm volatile("cp.async.cg.shared.global [%0], [%1], 16;" \
                 :: "r"(dst), "l"(src) : "memory")
#define CP_COMMIT() asm volatile("cp.async.commit_group;" ::: "memory")
#define CP_WAIT1()  asm volatile("cp.async.wait_group 1;" ::: "memory")

#define LDSM_X4(r, addr) \
    asm volatile("ldmatrix.sync.aligned.m8n8.x4.shared.b16 {%0,%1,%2,%3}, [%4];" \
        : "=r"((r)[0]), "=r"((r)[1]), "=r"((r)[2]), "=r"((r)[3]) : "r"(addr))
#define LDSM_X4T(r, addr) \
    asm volatile("ldmatrix.sync.aligned.m8n8.x4.trans.shared.b16 {%0,%1,%2,%3}, [%4];" \
        : "=r"((r)[0]), "=r"((r)[1]), "=r"((r)[2]), "=r"((r)[3]) : "r"(addr))

__device__ __forceinline__ void mma16(float* c, const uint32_t* a, uint32_t b0, uint32_t b1) {
    asm volatile(
        "mma.sync.aligned.m16n8k16.row.col.f32.f16.f16.f32 "
        "{%0,%1,%2,%3},{%4,%5,%6,%7},{%8,%9},{%0,%1,%2,%3};"
        : "+f"(c[0]), "+f"(c[1]), "+f"(c[2]), "+f"(c[3])
        : "r"(a[0]), "r"(a[1]), "r"(a[2]), "r"(a[3]), "r"(b0), "r"(b1));
}

__device__ __forceinline__ uint32_t pack_h2(float x, float y) {
    __half2 t = __floats2half2_rn(x, y);
    return *(uint32_t*)&t;
}

// ---------------- fp32 -> fp16 converter (all 4 weights, one launch) ----------------
#define CVT_N0 (DMODEL * 3 * DMODEL / 4)
#define CVT_N1 (DMODEL * DMODEL / 4)
#define CVT_N2 (DMODEL * DFF / 4)
__global__ void cvt_all(const float* __restrict__ wqkv, const float* __restrict__ wo,
                        const float* __restrict__ w1, const float* __restrict__ w2,
                        __half* __restrict__ oqkv, __half* __restrict__ owo,
                        __half* __restrict__ ow1, __half* __restrict__ ow2) {
    int idx = blockIdx.x * blockDim.x + threadIdx.x;
    const float* in;
    __half* out;
    int off;
    if (idx < CVT_N0)                          { in = wqkv; out = oqkv; off = idx; }
    else if (idx < CVT_N0 + CVT_N1)            { in = wo;   out = owo;  off = idx - CVT_N0; }
    else if (idx < CVT_N0 + CVT_N1 + CVT_N2)   { in = w1;   out = ow1;  off = idx - CVT_N0 - CVT_N1; }
    else                                       { in = w2;   out = ow2;  off = idx - CVT_N0 - CVT_N1 - CVT_N2; }
    float4 v = ((const float4*)in)[off];
    ((__half2*)out)[off * 2]     = __floats2half2_rn(v.x, v.y);
    ((__half2*)out)[off * 2 + 1] = __floats2half2_rn(v.z, v.w);
}

// ---------------- LayerNorm: fp32 x -> fp16 ln1, ln2 ----------------
__global__ void ln_kernel(const float* __restrict__ x,
                          const float* __restrict__ ga1, const float* __restrict__ be1,
                          const float* __restrict__ ga2, const float* __restrict__ be2,
                          __half* __restrict__ o1, __half* __restrict__ o2) {
    int t = blockIdx.x;
    int tid = threadIdx.x;
    const float4* xr = (const float4*)(x + (size_t)t * DMODEL);
    float4 a = xr[tid];
    float4 bq = xr[tid + 256];
    float s  = a.x + a.y + a.z + a.w + bq.x + bq.y + bq.z + bq.w;
    float s2 = a.x*a.x + a.y*a.y + a.z*a.z + a.w*a.w +
               bq.x*bq.x + bq.y*bq.y + bq.z*bq.z + bq.w*bq.w;
    #pragma unroll
    for (int o = 16; o; o >>= 1) {
        s  += __shfl_xor_sync(0xffffffffu, s,  o);
        s2 += __shfl_xor_sync(0xffffffffu, s2, o);
    }
    __shared__ float rs[8], rs2[8], stats[2];
    if ((tid & 31) == 0) { rs[tid >> 5] = s; rs2[tid >> 5] = s2; }
    __syncthreads();
    if (tid == 0) {
        float S = 0.f, S2 = 0.f;
        for (int i = 0; i < 8; i++) { S += rs[i]; S2 += rs2[i]; }
        float mu = S * (1.0f / DMODEL);
        float var = S2 * (1.0f / DMODEL) - mu * mu;
        stats[0] = mu;
        stats[1] = rsqrtf(var + 1e-5f);
    }
    __syncthreads();
    float mu = stats[0], r = stats[1];
    const float4* G1 = (const float4*)ga1;
    const float4* B1 = (const float4*)be1;
    const float4* G2 = (const float4*)ga2;
    const float4* B2 = (const float4*)be2;
    __half2* O1 = (__half2*)(o1 + (size_t)t * DMODEL);
    __half2* O2 = (__half2*)(o2 + (size_t)t * DMODEL);
    #pragma unroll
    for (int i = 0; i < 2; i++) {
        int idx = tid + i * 256;
        float4 v = (i == 0) ? a : bq;
        float nx = (v.x - mu) * r, ny = (v.y - mu) * r, nz = (v.z - mu) * r, nw = (v.w - mu) * r;
        float4 g1v = G1[idx], b1v = B1[idx], g2v = G2[idx], b2v = B2[idx];
        O1[idx * 2]     = __floats2half2_rn(nx * g1v.x + b1v.x, ny * g1v.y + b1v.y);
        O1[idx * 2 + 1] = __floats2half2_rn(nz * g1v.z + b1v.z, nw * g1v.w + b1v.w);
        O2[idx * 2]     = __floats2half2_rn(nx * g2v.x + b2v.x, ny * g2v.y + b2v.y);
        O2[idx * 2 + 1] = __floats2half2_rn(nz * g2v.z + b2v.z, nw * g2v.w + b2v.w);
    }
}

// ---------------- mask flag ----------------
__global__ void flag_init(int* flag) { if (threadIdx.x == 0) flag[0] = 1; }

__global__ void mask_reduce(const int* __restrict__ mask, int n, int* __restrict__ flag) {
    bool bad = false;
    for (int i = blockIdx.x * blockDim.x + threadIdx.x; i < n; i += gridDim.x * blockDim.x)
        if (bad |= (mask[i] == 0), false) {}
    if (bad) flag[0] = 0;
}

// ======== fp16 GEMM: 128x128 tile, K-chunk 64, 3 stages, 256 threads, 2 CTAs/SM ========
#define A_ROWB  144                 // 64 halfs + 16B pad
#define A_BYTES (128 * A_ROWB)      // 18432
#define B_ROWB  272                 // 128 halfs + 16B pad
#define B_BYTES (64 * B_ROWB)       // 17408
#define STAGE   (A_BYTES + B_BYTES) // 35840
#define NSTAGE  3
#define SMEM_GEMM (STAGE * NSTAGE)  // 107520 -> 2 CTAs/SM

struct Epi {
    const float* c0;   // bias
    const float* c1;   // layer_scale
    const float* c2;   // x residual
    float* o0;         // fp32 out
    __half* bo0;
    __half* bo1;
    __half* bo2;
};

// E=0: QKV head split.  E=1: out += v (WO accumulate).
// E=2: h = gelu(v + b1). E=3: out = x + ls*(v + b2) (FF2 init).
template <int E>
__device__ __forceinline__ void emit2(int r, int c, int N, float v0, float v1, const Epi& e) {
    if (E == 0) {
        int which = c >> 11, hh = (c >> 7) & 15, d0 = c & 127;
        __half* dst = (which == 0) ? e.bo0 : ((which == 1) ? e.bo1 : e.bo2);
        int b = r >> 11, s = r & 2047;
        __half* p = dst + (size_t)((b << 4) + hh) * (SEQ * DKH) + (size_t)s * DKH + d0;
        *(__half2*)p = __floats2half2_rn(v0, v1);
    } else if (E == 1) {
        size_t i = (size_t)r * N + c;
        float2 o = *(const float2*)(e.o0 + i);
        o.x += v0;
        o.y += v1;
        *(float2*)(e.o0 + i) = o;
    } else if (E == 2) {
        const float is2 = 0.70710678118654752f;
        float t0 = v0 + e.c0[c], t1 = v1 + e.c0[c + 1];
        float g0 = 0.5f * t0 * (1.0f + erff(t0 * is2));
        float g1 = 0.5f * t1 * (1.0f + erff(t1 * is2));
        __half* p = e.bo0 + (size_t)r * N + c;
        *(__half2*)p = __floats2half2_rn(g0, g1);
    } else {
        size_t i = (size_t)r * N + c;
        float2 xv = *(const float2*)(e.c2 + i);
        float2 bb = *(const float2*)(e.c0 + c);
        float2 ls = *(const float2*)(e.c1 + c);
        float2 o;
        o.x = xv.x + ls.x * (v0 + bb.x);
        o.y = xv.y + ls.y * (v1 + bb.y);
        *(float2*)(e.o0 + i) = o;
    }
}

__device__ __forceinline__ void gemm_load_stage(const __half* A, const __half* B,
                                                int K, int N, int bm, int bn, int kt,
                                                uint32_t base, int tid) {
    // A: 128 rows x 64 halfs = 1024 16B-chunks (4/thread)
    #pragma unroll
    for (int t = 0; t < 4; t++) {
        int c = tid + t * 256;
        int row = c >> 3, k8 = c & 7;
        const __half* src = A + (size_t)(bm + row) * K + kt * 64 + k8 * 8;
        CP16(base + (uint32_t)row * A_ROWB + (uint32_t)k8 * 16, src);
    }
    // B: 64 rows x 128 halfs = 1024 16B-chunks (4/thread)
    #pragma unroll
    for (int t = 0; t < 4; t++) {
        int c = tid + t * 256;
        int row = c >> 4, n8 = c & 15;
        const __half* src = B + (size_t)(kt * 64 + row) * N + bn + n8 * 8;
        CP16(base + A_BYTES + (uint32_t)row * B_ROWB + (uint32_t)n8 * 16, src);
    }
    CP_COMMIT();
}

template <int E>
__global__ __launch_bounds__(256, 2)
void gemm_f16(const __half* __restrict__ A, const __half* __restrict__ B,
              int M, int N, int K, Epi e) {
    extern __shared__ __align__(128) char smc[];
    uint32_t smb = smem_u32(smc);
    int tid = threadIdx.x, warp = tid >> 5, lane = tid & 31;
    int bm = blockIdx.y * 128, bn = blockIdx.x * 128;
    int wm = (warp >> 1) * 32, wn = (warp & 1) * 64;
    const int nt = K >> 6;

    float acc[2][8][4];
    #pragma unroll
    for (int i = 0; i < 2; i++)
        #pragma unroll
        for (int j = 0; j < 8; j++)
            #pragma unroll
            for (int k = 0; k < 4; k++) acc[i][j][k] = 0.f;

    gemm_load_stage(A, B, K, N, bm, bn, 0, smb, tid);
    gemm_load_stage(A, B, K, N, bm, bn, 1, smb + STAGE, tid);

    int frow = (lane & 7) + ((lane >> 3) & 1) * 8;
    int hi = lane >> 4;

    for (int i = 0; i < nt; i++) {
        CP_WAIT1();
        __syncthreads();
        if (i + 2 < nt)
            gemm_load_stage(A, B, K, N, bm, bn, i + 2, smb + (uint32_t)((i + 2) % 3) * STAGE, tid);

        uint32_t abase = smb + (uint32_t)(i % 3) * STAGE;
        uint32_t bbase = abase + A_BYTES;
        #pragma unroll
        for (int k16 = 0; k16 < 4; k16++) {
            uint32_t a[2][4], bf[4][4];
            #pragma unroll
            for (int mt = 0; mt < 2; mt++) {
                uint32_t ad = abase + (uint32_t)(wm + mt * 16 + frow) * A_ROWB
                            + (uint32_t)(k16 * 2 + hi) * 16;
                LDSM_X4(a[mt], ad);
            }
            #pragma unroll
            for (int nt16 = 0; nt16 < 4; nt16++) {
                uint32_t bd = bbase + (uint32_t)(k16 * 16 + frow) * B_ROWB
                            + (uint32_t)(((wn + nt16 * 16) >> 3) + hi) * 16;
                LDSM_X4T(bf[nt16], bd);
            }
            #pragma unroll
            for (int mt = 0; mt < 2; mt++)
                #pragma unroll
                for (int n8 = 0; n8 < 8; n8++)
                    mma16(acc[mt][n8], a[mt], bf[n8 >> 1][(n8 & 1) * 2], bf[n8 >> 1][(n8 & 1) * 2 + 1]);
        }
    }

    int g = lane >> 2, tq = lane & 3;
    #pragma unroll
    for (int mt = 0; mt < 2; mt++) {
        int r0 = bm + wm + mt * 16 + g;
        #pragma unroll
        for (int n8 = 0; n8 < 8; n8++) {
            int c0 = bn + wn + n8 * 8 + tq * 2;
            emit2<E>(r0,     c0, N, acc[mt][n8][0], acc[mt][n8][1], e);
            emit2<E>(r0 + 8, c0, N, acc[mt][n8][2], acc[mt][n8][3], e);
        }
    }
}

// ======== flash attention: fp16 mma16 + ldmatrix, single fp16 P ========
#define AKV_ROWB 272
#define AKV_MATB 17408
#define ATTN_SMEM (AKV_MATB * 5)

__global__ __launch_bounds__(128, 2)
void attn_f16(const __half* __restrict__ Q, const __half* __restrict__ K,
              const __half* __restrict__ V, const int* __restrict__ mask,
              const int* __restrict__ flag, __half* __restrict__ ctx) {
    extern __shared__ __align__(128) char sma[];
    uint32_t smb = smem_u32(sma);
    int tid = threadIdx.x, warp = tid >> 5, lane = tid & 31;
    int g = lane >> 2, tq = lane & 3;
    int frow = (lane & 7) + ((lane >> 3) & 1) * 8;
    int hi = lane >> 4;
    int qt = blockIdx.x, bh = blockIdx.y;
    int b = bh >> 4, h = bh & 15;
    const __half* Qg = Q + (size_t)bh * SEQ * DKH + (size_t)(qt * 64) * DKH;
    const __half* Kg = K + (size_t)bh * SEQ * DKH;
    const __half* Vg = V + (size_t)bh * SEQ * DKH;
    int q0 = qt * 64 + warp * 16;
    int allv = flag[0];

    {
        int row = tid >> 1, c16b = (tid & 1) * 8;
        #pragma unroll
        for (int t = 0; t < 8; t++) {
            CP16(smb + (uint32_t)row * AKV_ROWB + (uint32_t)(c16b + t) * 16,
                 Qg + (size_t)row * DKH + (c16b + t) * 8);
        }
        #pragma unroll
        for (int t = 0; t < 8; t++) {
            CP16(smb + AKV_MATB + (uint32_t)row * AKV_ROWB + (uint32_t)(c16b + t) * 16,
                 Kg + (size_t)row * DKH + (c16b + t) * 8);
            CP16(smb + AKV_MATB + AKV_MATB + (uint32_t)row * AKV_ROWB + (uint32_t)(c16b + t) * 16,
                 Vg + (size_t)row * DKH + (c16b + t) * 8);
        }
        CP_COMMIT();
        #pragma unroll
        for (int t = 0; t < 8; t++) {
            CP16(smb + AKV_MATB * 3 + (uint32_t)row * AKV_ROWB + (uint32_t)(c16b + t) * 16,
                 Kg + (size_t)(64 + row) * DKH + (c16b + t) * 8);
            CP16(smb + AKV_MATB * 4 + (uint32_t)row * AKV_ROWB + (uint32_t)(c16b + t) * 16,
                 Vg + (size_t)(64 + row) * DKH + (c16b + t) * 8);
        }
        CP_COMMIT();
    }

    CP_WAIT1();
    __syncthreads();

    uint32_t qa[8][4];
    #pragma unroll
    for (int k16 = 0; k16 < 8; k16++)
        LDSM_X4(qa[k16], smb + (uint32_t)(warp * 16 + frow) * AKV_ROWB
                             + (uint32_t)(k16 * 2 + hi) * 16);

    float o[16][4];
    #pragma unroll
    for (int i = 0; i < 16; i++)
        #pragma unroll
        for (int j = 0; j < 4; j++) o[i][j] = 0.f;
    float mA = -1e30f, mB = -1e30f, lA = 0.f, lB = 0.f;

    for (int j = 0; j < 32; j++) {
        if (j > 0) { CP_WAIT1(); __syncthreads(); }
        int buf = j & 1;
        uint32_t kbase = smb + AKV_MATB + (uint32_t)buf * (2 * AKV_MATB);
        uint32_t vbase = kbase + AKV_MATB;

        float sc[8][4];
        #pragma unroll
        for (int ni = 0; ni < 8; ni++)
            #pragma unroll
            for (int c = 0; c < 4; c++) sc[ni][c] = 0.f;
        #pragma unroll
        for (int k16 = 0; k16 < 8; k16++) {
            #pragma unroll
            for (int n16 = 0; n16 < 4; n16++) {
                uint32_t kb[4];
                LDSM_X4(kb, kbase + (uint32_t)(n16 * 16 + frow) * AKV_ROWB
                                  + (uint32_t)(k16 * 2 + hi) * 16);
                mma16(sc[n16 * 2],     qa[k16], kb[0], kb[2]);
                mma16(sc[n16 * 2 + 1], qa[k16], kb[1], kb[3]);
            }
        }
        const float sscale = 0.0883883476483184f;
        #pragma unroll
        for (int ni = 0; ni < 8; ni++)
            #pragma unroll
            for (int c = 0; c < 4; c++) sc[ni][c] *= sscale;

        if (!allv) {
            #pragma unroll
            for (int ni = 0; ni < 8; ni++) {
                int kc = j * 64 + ni * 8 + tq * 2;
                int r0 = q0 + g, r1 = q0 + g + 8;
                if (mask[(size_t)r0 * SEQ + kc] == 0)     sc[ni][0] = -1e9f;
                if (mask[(size_t)r0 * SEQ + kc + 1] == 0) sc[ni][1] = -1e9f;
                if (mask[(size_t)r1 * SEQ + kc] == 0)     sc[ni][2] = -1e9f;
                if (mask[(size_t)r1 * SEQ + kc + 1] == 0) sc[ni][3] = -1e9f;
            }
        }

        float mxA = -1e30f, mxB = -1e30f;
        #pragma unroll
        for (int ni = 0; ni < 8; ni++) {
            mxA = fmaxf(mxA, fmaxf(sc[ni][0], sc[ni][1]));
            mxB = fmaxf(mxB, fmaxf(sc[ni][2], sc[ni][3]));
        }
        mxA = fmaxf(mxA, __shfl_xor_sync(0xffffffffu, mxA, 1));
        mxA = fmaxf(mxA, __shfl_xor_sync(0xffffffffu, mxA, 2));
        mxB = fmaxf(mxB, __shfl_xor_sync(0xffffffffu, mxB, 1));
        mxB = fmaxf(mxB, __shfl_xor_sync(0xffffffffu, mxB, 2));
        float mAn = fmaxf(mA, mxA), mBn = fmaxf(mB, mxB);
        float aA = __expf(mA - mAn), aB = __expf(mB - mBn);
        float sA = 0.f, sB = 0.f;
        #pragma unroll
        for (int ni = 0; ni < 8; ni++) {
            sc[ni][0] = __expf(sc[ni][0] - mAn); sA += sc[ni][0];
            sc[ni][1] = __expf(sc[ni][1] - mAn); sA += sc[ni][1];
            sc[ni][2] = __expf(sc[ni][2] - mBn); sB += sc[ni][2];
            sc[ni][3] = __expf(sc[ni][3] - mBn); sB += sc[ni][3];
        }
        sA += __shfl_xor_sync(0xffffffffu, sA, 1);
        sA += __shfl_xor_sync(0xffffffffu, sA, 2);
        sB += __shfl_xor_sync(0xffffffffu, sB, 1);
        sB += __shfl_xor_sync(0xffffffffu, sB, 2);
        lA = lA * aA + sA;
        lB = lB * aB + sB;
        mA = mAn; mB = mBn;
        #pragma unroll
        for (int ni = 0; ni < 16; ni++) {
            o[ni][0] *= aA; o[ni][1] *= aA;
            o[ni][2] *= aB; o[ni][3] *= aB;
        }

        uint32_t pa[4][4];
        #pragma unroll
        for (int jj = 0; jj < 4; jj++) {
            float* e0 = sc[2 * jj];
            float* e1 = sc[2 * jj + 1];
            pa[jj][0] = pack_h2(e0[0], e0[1]);
            pa[jj][1] = pack_h2(e0[2], e0[3]);
            pa[jj][2] = pack_h2(e1[0], e1[1]);
            pa[jj][3] = pack_h2(e1[2], e1[3]);
        }

        #pragma unroll
        for (int k16 = 0; k16 < 4; k16++) {
            #pragma unroll
            for (int n16 = 0; n16 < 8; n16++) {
                uint32_t vb4[4];
                LDSM_X4T(vb4, vbase + (uint32_t)(k16 * 16 + frow) * AKV_ROWB
                                    + (uint32_t)(n16 * 2 + hi) * 16);
                mma16(o[n16 * 2],     pa[k16], vb4[0], vb4[1]);
                mma16(o[n16 * 2 + 1], pa[k16], vb4[2], vb4[3]);
            }
        }

        __syncthreads();
        if (j + 2 < 32) {
            int row = tid >> 1, c16b = (tid & 1) * 8;
            uint32_t kd = smb + AKV_MATB + (uint32_t)buf * (2 * AKV_MATB);
            const __half* ks = Kg + (size_t)((j + 2) * 64 + row) * DKH;
            const __half* vs = Vg + (size_t)((j + 2) * 64 + row) * DKH;
            #pragma unroll
            for (int t = 0; t < 8; t++) {
                CP16(kd + (uint32_t)row * AKV_ROWB + (uint32_t)(c16b + t) * 16,
                     ks + (c16b + t) * 8);
                CP16(kd + AKV_MATB + (uint32_t)row * AKV_ROWB + (uint32_t)(c16b + t) * 16,
                     vs + (c16b + t) * 8);
            }
            CP_COMMIT();
        }
    }

    float rA = 1.f / lA, rB = 1.f / lB;
    int tok0 = b * SEQ + q0 + g, tok1 = tok0 + 8;
    #pragma unroll
    for (int ni = 0; ni < 16; ni++) {
        int d = ni * 8 + tq * 2;
        __half* p0 = ctx + (size_t)tok0 * DMODEL + h * DKH + d;
        __half* p1 = ctx + (size_t)tok1 * DMODEL + h * DKH + d;
        *(__half2*)p0 = __floats2half2_rn(o[ni][0] * rA, o[ni][1] * rA);
        *(__half2*)p1 = __floats2half2_rn(o[ni][2] * rB, o[ni][3] * rB);
    }
}

// ---------------- launch ----------------
extern "C" void kernel_launch(void* const* d_in, const int* in_sizes, int n_in,
                              void* d_out, int out_size) {
    const float* x     = (const float*)d_in[0];
    const int*   mask  = (const int*)d_in[1];
    const float* w_qkv = (const float*)d_in[2];
    const float* w_o   = (const float*)d_in[3];
    const float* ga1   = (const float*)d_in[4];
    const float* be1   = (const float*)d_in[5];
    const float* ga2   = (const float*)d_in[6];
    const float* be2   = (const float*)d_in[7];
    const float* w1    = (const float*)d_in[8];
    const float* b1    = (const float*)d_in[9];
    const float* w2    = (const float*)d_in[10];
    const float* b2    = (const float*)d_in[11];
    const float* ls    = (const float*)d_in[12];
    float* out = (float*)d_out;

    __half *ln1, *ln2, *q, *k, *v, *ctx, *hbuf, *wqkvb, *wob, *w1b, *w2b;
    int* flag;
    cudaGetSymbolAddress((void**)&ln1,   g_ln1);
    cudaGetSymbolAddress((void**)&ln2,   g_ln2);
    cudaGetSymbolAddress((void**)&q,     g_q);
    cudaGetSymbolAddress((void**)&k,     g_k);
    cudaGetSymbolAddress((void**)&v,     g_v);
    cudaGetSymbolAddress((void**)&ctx,   g_ctx);
    cudaGetSymbolAddress((void**)&hbuf,  g_h);
    cudaGetSymbolAddress((void**)&wqkvb, g_wqkv);
    cudaGetSymbolAddress((void**)&wob,   g_wo);
    cudaGetSymbolAddress((void**)&w1b,   g_w1);
    cudaGetSymbolAddress((void**)&w2b,   g_w2);
    cudaGetSymbolAddress((void**)&flag,  g_flag);

    cudaFuncSetAttribute(attn_f16, cudaFuncAttributeMaxDynamicSharedMemorySize, ATTN_SMEM);
    cudaFuncSetAttribute(gemm_f16<0>, cudaFuncAttributeMaxDynamicSharedMemorySize, SMEM_GEMM);
    cudaFuncSetAttribute(gemm_f16<1>, cudaFuncAttributeMaxDynamicSharedMemorySize, SMEM_GEMM);
    cudaFuncSetAttribute(gemm_f16<2>, cudaFuncAttributeMaxDynamicSharedMemorySize, SMEM_GEMM);
    cudaFuncSetAttribute(gemm_f16<3>, cudaFuncAttributeMaxDynamicSharedMemorySize, SMEM_GEMM);

    // side stream + events (host resources only; created once)
    static cudaStream_t s2 = nullptr;
    static cudaEvent_t evA = nullptr, evC = nullptr, evB = nullptr;
    if (s2 == nullptr) {
        cudaStreamCreateWithFlags(&s2, cudaStreamNonBlocking);
        cudaEventCreateWithFlags(&evA, cudaEventDisableTiming);
        cudaEventCreateWithFlags(&evC, cudaEventDisableTiming);
        cudaEventCreateWithFlags(&evB, cudaEventDisableTiming);
    }

    // ---- main stream: conversions + layernorm ----
    cvt_all<<<(CVT_N0 + CVT_N1 + 2 * CVT_N2) / 256, 256>>>(
        w_qkv, w_o, w1, w2, wqkvb, wob, w1b, w2b);
    ln_kernel<<<TOKS, 256>>>(x, ga1, be1, ga2, be2, ln1, ln2);
    cudaEventRecord(evA, 0);

    // ---- side stream: QKV projection ----
    cudaStreamWaitEvent(s2, evA, 0);
    Epi e1 = {nullptr, nullptr, nullptr, nullptr, q, k, v};
    gemm_f16<0><<<dim3(48, 32), 256, SMEM_GEMM, s2>>>(ln1, wqkvb, TOKS, 3 * DMODEL, DMODEL, e1);

    // ---- main: FF1 (ncu capture slot) ----
    Epi e3 = {b1, nullptr, nullptr, nullptr, hbuf, nullptr, nullptr};
    gemm_f16<2><<<dim3(64, 32), 256, SMEM_GEMM>>>(ln2, w1b, TOKS, DFF, DMODEL, e3);

    // ---- main: mask flag ----
    flag_init<<<1, 32>>>(flag);
    mask_reduce<<<256, 256>>>(mask, in_sizes[1], flag);
    cudaEventRecord(evC, 0);

    // ---- side: attention (needs QKV + mask flag) ----
    cudaStreamWaitEvent(s2, evC, 0);
    attn_f16<<<dim3(32, 32), 128, ATTN_SMEM, s2>>>(q, k, v, mask, flag, ctx);
    cudaEventRecord(evB, s2);

    // ---- main: FF2 initializes out = x + ls*(h@w2 + b2) ----
    Epi e4 = {b2, ls, x, out, nullptr, nullptr, nullptr};
    gemm_f16<3><<<dim3(16, 32), 256, SMEM_GEMM>>>(hbuf, w2b, TOKS, DMODEL, DFF, e4);

    // ---- join, then WO accumulates out += ctx @ w_o ----
    cudaStreamWaitEvent(0, evB, 0);
    Epi e2 = {nullptr, nullptr, nullptr, out, nullptr, nullptr, nullptr};
    gemm_f16<1><<<dim3(16, 32), 256, SMEM_GEMM>>>(ctx, wob, TOKS, DMODEL, DMODEL, e2);
}

// round 13
// speedup vs baseline: 1.1598x; 1.0678x over previous
#include <cuda_runtime.h>
#include <cuda_fp16.h>
#include <cstdint>
#include <cmath>

// ---------------- problem constants ----------------
#define TOKS 4096
#define DMODEL 2048
#define DFF 8192
#define NHEADS 16
#define DKH 128
#define SEQ 2048
#define BATCH 2

// ---------------- scratch (device globals) ----------------
__device__ __align__(128) __half g_ln1[TOKS * DMODEL];
__device__ __align__(128) __half g_ln2[TOKS * DMODEL];
__device__ __align__(128) __half g_q[TOKS * DMODEL];
__device__ __align__(128) __half g_k[TOKS * DMODEL];
__device__ __align__(128) __half g_v[TOKS * DMODEL];
__device__ __align__(128) __half g_ctx[TOKS * DMODEL];
__device__ __align__(128) __half g_h[TOKS * DFF];
__device__ __align__(128) __half g_wqkv[DMODEL * 3 * DMODEL];
__device__ __align__(128) __half g_wo[DMODEL * DMODEL];
__device__ __align__(128) __half g_w1[DMODEL * DFF];
__device__ __align__(128) __half g_w2[DFF * DMODEL];
__device__ int g_flag[1];

// ---------------- helpers ----------------
__device__ __forceinline__ uint32_t smem_u32(const void* p) {
    uint32_t a;
    asm("{ .reg .u64 t; cvta.to.shared.u64 t, %1; cvt.u32.u64 %0, t; }"
        : "=r"(a) : "l"(p));
    return a;
}

#define CP16(dst, src) \
    asm volatile("cp.async.cg.shared.global [%0], [%1], 16;" \
                 :: "r"(dst), "l"(src) : "memory")
#define CP_COMMIT() asm volatile("cp.async.commit_group;" ::: "memory")
#define CP_WAIT1()  asm volatile("cp.async.wait_group 1;" ::: "memory")

#define LDSM_X4(r, addr) \
    asm volatile("ldmatrix.sync.aligned.m8n8.x4.shared.b16 {%0,%1,%2,%3}, [%4];" \
        : "=r"((r)[0]), "=r"((r)[1]), "=r"((r)[2]), "=r"((r)[3]) : "r"(addr))
#define LDSM_X4T(r, addr) \
    asm volatile("ldmatrix.sync.aligned.m8n8.x4.trans.shared.b16 {%0,%1,%2,%3}, [%4];" \
        : "=r"((r)[0]), "=r"((r)[1]), "=r"((r)[2]), "=r"((r)[3]) : "r"(addr))

__device__ __forceinline__ void mma16(float* c, const uint32_t* a, uint32_t b0, uint32_t b1) {
    asm volatile(
        "mma.sync.aligned.m16n8k16.row.col.f32.f16.f16.f32 "
        "{%0,%1,%2,%3},{%4,%5,%6,%7},{%8,%9},{%0,%1,%2,%3};"
        : "+f"(c[0]), "+f"(c[1]), "+f"(c[2]), "+f"(c[3])
        : "r"(a[0]), "r"(a[1]), "r"(a[2]), "r"(a[3]), "r"(b0), "r"(b1));
}

__device__ __forceinline__ uint32_t pack_h2(float x, float y) {
    __half2 t = __floats2half2_rn(x, y);
    return *(uint32_t*)&t;
}

// ---------------- fp32 -> fp16 converter (all 4 weights, one launch) ----------------
#define CVT_N0 (DMODEL * 3 * DMODEL / 4)
#define CVT_N1 (DMODEL * DMODEL / 4)
#define CVT_N2 (DMODEL * DFF / 4)
__global__ void cvt_all(const float* __restrict__ wqkv, const float* __restrict__ wo,
                        const float* __restrict__ w1, const float* __restrict__ w2,
                        __half* __restrict__ oqkv, __half* __restrict__ owo,
                        __half* __restrict__ ow1, __half* __restrict__ ow2) {
    int idx = blockIdx.x * blockDim.x + threadIdx.x;
    const float* in;
    __half* out;
    int off;
    if (idx < CVT_N0)                          { in = wqkv; out = oqkv; off = idx; }
    else if (idx < CVT_N0 + CVT_N1)            { in = wo;   out = owo;  off = idx - CVT_N0; }
    else if (idx < CVT_N0 + CVT_N1 + CVT_N2)   { in = w1;   out = ow1;  off = idx - CVT_N0 - CVT_N1; }
    else                                       { in = w2;   out = ow2;  off = idx - CVT_N0 - CVT_N1 - CVT_N2; }
    float4 v = ((const float4*)in)[off];
    ((__half2*)out)[off * 2]     = __floats2half2_rn(v.x, v.y);
    ((__half2*)out)[off * 2 + 1] = __floats2half2_rn(v.z, v.w);
}

// ---------------- LayerNorm: fp32 x -> fp16 ln1, ln2 ----------------
__global__ void ln_kernel(const float* __restrict__ x,
                          const float* __restrict__ ga1, const float* __restrict__ be1,
                          const float* __restrict__ ga2, const float* __restrict__ be2,
                          __half* __restrict__ o1, __half* __restrict__ o2) {
    int t = blockIdx.x;
    int tid = threadIdx.x;
    const float4* xr = (const float4*)(x + (size_t)t * DMODEL);
    float4 a = xr[tid];
    float4 bq = xr[tid + 256];
    float s  = a.x + a.y + a.z + a.w + bq.x + bq.y + bq.z + bq.w;
    float s2 = a.x*a.x + a.y*a.y + a.z*a.z + a.w*a.w +
               bq.x*bq.x + bq.y*bq.y + bq.z*bq.z + bq.w*bq.w;
    #pragma unroll
    for (int o = 16; o; o >>= 1) {
        s  += __shfl_xor_sync(0xffffffffu, s,  o);
        s2 += __shfl_xor_sync(0xffffffffu, s2, o);
    }
    __shared__ float rs[8], rs2[8], stats[2];
    if ((tid & 31) == 0) { rs[tid >> 5] = s; rs2[tid >> 5] = s2; }
    __syncthreads();
    if (tid == 0) {
        float S = 0.f, S2 = 0.f;
        for (int i = 0; i < 8; i++) { S += rs[i]; S2 += rs2[i]; }
        float mu = S * (1.0f / DMODEL);
        float var = S2 * (1.0f / DMODEL) - mu * mu;
        stats[0] = mu;
        stats[1] = rsqrtf(var + 1e-5f);
    }
    __syncthreads();
    float mu = stats[0], r = stats[1];
    const float4* G1 = (const float4*)ga1;
    const float4* B1 = (const float4*)be1;
    const float4* G2 = (const float4*)ga2;
    const float4* B2 = (const float4*)be2;
    __half2* O1 = (__half2*)(o1 + (size_t)t * DMODEL);
    __half2* O2 = (__half2*)(o2 + (size_t)t * DMODEL);
    #pragma unroll
    for (int i = 0; i < 2; i++) {
        int idx = tid + i * 256;
        float4 v = (i == 0) ? a : bq;
        float nx = (v.x - mu) * r, ny = (v.y - mu) * r, nz = (v.z - mu) * r, nw = (v.w - mu) * r;
        float4 g1v = G1[idx], b1v = B1[idx], g2v = G2[idx], b2v = B2[idx];
        O1[idx * 2]     = __floats2half2_rn(nx * g1v.x + b1v.x, ny * g1v.y + b1v.y);
        O1[idx * 2 + 1] = __floats2half2_rn(nz * g1v.z + b1v.z, nw * g1v.w + b1v.w);
        O2[idx * 2]     = __floats2half2_rn(nx * g2v.x + b2v.x, ny * g2v.y + b2v.y);
        O2[idx * 2 + 1] = __floats2half2_rn(nz * g2v.z + b2v.z, nw * g2v.w + b2v.w);
    }
}

// ---------------- mask flag ----------------
__global__ void flag_init(int* flag) { if (threadIdx.x == 0) flag[0] = 1; }

__global__ void mask_reduce(const int* __restrict__ mask, int n, int* __restrict__ flag) {
    bool bad = false;
    for (int i = blockIdx.x * blockDim.x + threadIdx.x; i < n; i += gridDim.x * blockDim.x)
        if (mask[i] == 0) bad = true;
    if (bad) flag[0] = 0;
}

// ======== fp16 GEMM: 128x128 tile, K-chunk 64, 3 stages, 256 threads, 2 CTAs/SM ========
#define A_ROWB  144                 // 64 halfs + 16B pad
#define A_BYTES (128 * A_ROWB)      // 18432
#define B_ROWB  272                 // 128 halfs + 16B pad
#define B_BYTES (64 * B_ROWB)       // 17408
#define STAGE   (A_BYTES + B_BYTES) // 35840
#define NSTAGE  3
#define SMEM_GEMM (STAGE * NSTAGE)  // 107520 -> 2 CTAs/SM

struct Epi {
    const float* c0;   // bias
    const float* c1;   // layer_scale
    const float* c2;   // x residual
    float* o0;         // fp32 out
    __half* bo0;
    __half* bo1;
    __half* bo2;
};

// E=0: QKV head split.  E=1: out += v (WO accumulate).
// E=2: h = gelu(v + b1). E=3: out = x + ls*(v + b2) (FF2 init).
template <int E>
__device__ __forceinline__ void emit2(int r, int c, int N, float v0, float v1, const Epi& e) {
    if (E == 0) {
        int which = c >> 11, hh = (c >> 7) & 15, d0 = c & 127;
        __half* dst = (which == 0) ? e.bo0 : ((which == 1) ? e.bo1 : e.bo2);
        int b = r >> 11, s = r & 2047;
        __half* p = dst + (size_t)((b << 4) + hh) * (SEQ * DKH) + (size_t)s * DKH + d0;
        *(__half2*)p = __floats2half2_rn(v0, v1);
    } else if (E == 1) {
        size_t i = (size_t)r * N + c;
        float2 o = *(const float2*)(e.o0 + i);
        o.x += v0;
        o.y += v1;
        *(float2*)(e.o0 + i) = o;
    } else if (E == 2) {
        const float is2 = 0.70710678118654752f;
        float t0 = v0 + e.c0[c], t1 = v1 + e.c0[c + 1];
        float g0 = 0.5f * t0 * (1.0f + erff(t0 * is2));
        float g1 = 0.5f * t1 * (1.0f + erff(t1 * is2));
        __half* p = e.bo0 + (size_t)r * N + c;
        *(__half2*)p = __floats2half2_rn(g0, g1);
    } else {
        size_t i = (size_t)r * N + c;
        float2 xv = *(const float2*)(e.c2 + i);
        float2 bb = *(const float2*)(e.c0 + c);
        float2 ls = *(const float2*)(e.c1 + c);
        float2 o;
        o.x = xv.x + ls.x * (v0 + bb.x);
        o.y = xv.y + ls.y * (v1 + bb.y);
        *(float2*)(e.o0 + i) = o;
    }
}

__device__ __forceinline__ void gemm_load_stage(const __half* A, const __half* B,
                                                int K, int N, int bm, int bn, int kt,
                                                uint32_t base, int tid) {
    #pragma unroll
    for (int t = 0; t < 4; t++) {
        int c = tid + t * 256;
        int row = c >> 3, k8 = c & 7;
        const __half* src = A + (size_t)(bm + row) * K + kt * 64 + k8 * 8;
        CP16(base + (uint32_t)row * A_ROWB + (uint32_t)k8 * 16, src);
    }
    #pragma unroll
    for (int t = 0; t < 4; t++) {
        int c = tid + t * 256;
        int row = c >> 4, n8 = c & 15;
        const __half* src = B + (size_t)(kt * 64 + row) * N + bn + n8 * 8;
        CP16(base + A_BYTES + (uint32_t)row * B_ROWB + (uint32_t)n8 * 16, src);
    }
    CP_COMMIT();
}

template <int E>
__global__ __launch_bounds__(256, 2)
void gemm_f16(const __half* __restrict__ A, const __half* __restrict__ B,
              int M, int N, int K, Epi e) {
    extern __shared__ __align__(128) char smc[];
    uint32_t smb = smem_u32(smc);
    int tid = threadIdx.x, warp = tid >> 5, lane = tid & 31;
    int bm = blockIdx.y * 128, bn = blockIdx.x * 128;
    int wm = (warp >> 1) * 32, wn = (warp & 1) * 64;
    const int nt = K >> 6;

    float acc[2][8][4];
    #pragma unroll
    for (int i = 0; i < 2; i++)
        #pragma unroll
        for (int j = 0; j < 8; j++)
            #pragma unroll
            for (int k = 0; k < 4; k++) acc[i][j][k] = 0.f;

    gemm_load_stage(A, B, K, N, bm, bn, 0, smb, tid);
    gemm_load_stage(A, B, K, N, bm, bn, 1, smb + STAGE, tid);

    int frow = (lane & 7) + ((lane >> 3) & 1) * 8;
    int hi = lane >> 4;

    for (int i = 0; i < nt; i++) {
        CP_WAIT1();
        __syncthreads();
        if (i + 2 < nt)
            gemm_load_stage(A, B, K, N, bm, bn, i + 2, smb + (uint32_t)((i + 2) % 3) * STAGE, tid);

        uint32_t abase = smb + (uint32_t)(i % 3) * STAGE;
        uint32_t bbase = abase + A_BYTES;
        #pragma unroll
        for (int k16 = 0; k16 < 4; k16++) {
            uint32_t a[2][4], bf[4][4];
            #pragma unroll
            for (int mt = 0; mt < 2; mt++) {
                uint32_t ad = abase + (uint32_t)(wm + mt * 16 + frow) * A_ROWB
                            + (uint32_t)(k16 * 2 + hi) * 16;
                LDSM_X4(a[mt], ad);
            }
            LDSM_X4T(bf[0], bbase + (uint32_t)(k16 * 16 + frow) * B_ROWB
                          + (uint32_t)((wn >> 3) + hi) * 16);
            // interleave: issue next B ldmatrix behind the MMAs consuming the previous one
            #pragma unroll
            for (int nt16 = 0; nt16 < 4; nt16++) {
                if (nt16 < 3) {
                    LDSM_X4T(bf[nt16 + 1], bbase + (uint32_t)(k16 * 16 + frow) * B_ROWB
                                         + (uint32_t)(((wn + (nt16 + 1) * 16) >> 3) + hi) * 16);
                }
                #pragma unroll
                for (int mt = 0; mt < 2; mt++) {
                    mma16(acc[mt][nt16 * 2],     a[mt], bf[nt16][0], bf[nt16][1]);
                    mma16(acc[mt][nt16 * 2 + 1], a[mt], bf[nt16][2], bf[nt16][3]);
                }
            }
        }
    }

    int g = lane >> 2, tq = lane & 3;
    #pragma unroll
    for (int mt = 0; mt < 2; mt++) {
        int r0 = bm + wm + mt * 16 + g;
        #pragma unroll
        for (int n8 = 0; n8 < 8; n8++) {
            int c0 = bn + wn + n8 * 8 + tq * 2;
            emit2<E>(r0,     c0, N, acc[mt][n8][0], acc[mt][n8][1], e);
            emit2<E>(r0 + 8, c0, N, acc[mt][n8][2], acc[mt][n8][3], e);
        }
    }
}

// ======== flash attention: fp16 mma16 + ldmatrix, single fp16 P ========
#define AKV_ROWB 272
#define AKV_MATB 17408
#define ATTN_SMEM (AKV_MATB * 5)

__global__ __launch_bounds__(128, 2)
void attn_f16(const __half* __restrict__ Q, const __half* __restrict__ K,
              const __half* __restrict__ V, const int* __restrict__ mask,
              const int* __restrict__ flag, __half* __restrict__ ctx) {
    extern __shared__ __align__(128) char sma[];
    uint32_t smb = smem_u32(sma);
    int tid = threadIdx.x, warp = tid >> 5, lane = tid & 31;
    int g = lane >> 2, tq = lane & 3;
    int frow = (lane & 7) + ((lane >> 3) & 1) * 8;
    int hi = lane >> 4;
    int qt = blockIdx.x, bh = blockIdx.y;
    int b = bh >> 4, h = bh & 15;
    const __half* Qg = Q + (size_t)bh * SEQ * DKH + (size_t)(qt * 64) * DKH;
    const __half* Kg = K + (size_t)bh * SEQ * DKH;
    const __half* Vg = V + (size_t)bh * SEQ * DKH;
    int q0 = qt * 64 + warp * 16;
    int allv = flag[0];

    {
        int row = tid >> 1, c16b = (tid & 1) * 8;
        #pragma unroll
        for (int t = 0; t < 8; t++) {
            CP16(smb + (uint32_t)row * AKV_ROWB + (uint32_t)(c16b + t) * 16,
                 Qg + (size_t)row * DKH + (c16b + t) * 8);
        }
        #pragma unroll
        for (int t = 0; t < 8; t++) {
            CP16(smb + AKV_MATB + (uint32_t)row * AKV_ROWB + (uint32_t)(c16b + t) * 16,
                 Kg + (size_t)row * DKH + (c16b + t) * 8);
            CP16(smb + AKV_MATB + AKV_MATB + (uint32_t)row * AKV_ROWB + (uint32_t)(c16b + t) * 16,
                 Vg + (size_t)row * DKH + (c16b + t) * 8);
        }
        CP_COMMIT();
        #pragma unroll
        for (int t = 0; t < 8; t++) {
            CP16(smb + AKV_MATB * 3 + (uint32_t)row * AKV_ROWB + (uint32_t)(c16b + t) * 16,
                 Kg + (size_t)(64 + row) * DKH + (c16b + t) * 8);
            CP16(smb + AKV_MATB * 4 + (uint32_t)row * AKV_ROWB + (uint32_t)(c16b + t) * 16,
                 Vg + (size_t)(64 + row) * DKH + (c16b + t) * 8);
        }
        CP_COMMIT();
    }

    CP_WAIT1();
    __syncthreads();

    uint32_t qa[8][4];
    #pragma unroll
    for (int k16 = 0; k16 < 8; k16++)
        LDSM_X4(qa[k16], smb + (uint32_t)(warp * 16 + frow) * AKV_ROWB
                             + (uint32_t)(k16 * 2 + hi) * 16);

    float o[16][4];
    #pragma unroll
    for (int i = 0; i < 16; i++)
        #pragma unroll
        for (int j = 0; j < 4; j++) o[i][j] = 0.f;
    float mA = -1e30f, mB = -1e30f, lA = 0.f, lB = 0.f;

    for (int j = 0; j < 32; j++) {
        if (j > 0) { CP_WAIT1(); __syncthreads(); }
        int buf = j & 1;
        uint32_t kbase = smb + AKV_MATB + (uint32_t)buf * (2 * AKV_MATB);
        uint32_t vbase = kbase + AKV_MATB;

        float sc[8][4];
        #pragma unroll
        for (int ni = 0; ni < 8; ni++)
            #pragma unroll
            for (int c = 0; c < 4; c++) sc[ni][c] = 0.f;
        #pragma unroll
        for (int k16 = 0; k16 < 8; k16++) {
            #pragma unroll
            for (int n16 = 0; n16 < 4; n16++) {
                uint32_t kb[4];
                LDSM_X4(kb, kbase + (uint32_t)(n16 * 16 + frow) * AKV_ROWB
                                  + (uint32_t)(k16 * 2 + hi) * 16);
                mma16(sc[n16 * 2],     qa[k16], kb[0], kb[2]);
                mma16(sc[n16 * 2 + 1], qa[k16], kb[1], kb[3]);
            }
        }
        const float sscale = 0.0883883476483184f;
        #pragma unroll
        for (int ni = 0; ni < 8; ni++)
            #pragma unroll
            for (int c = 0; c < 4; c++) sc[ni][c] *= sscale;

        if (!allv) {
            #pragma unroll
            for (int ni = 0; ni < 8; ni++) {
                int kc = j * 64 + ni * 8 + tq * 2;
                int r0 = q0 + g, r1 = q0 + g + 8;
                if (mask[(size_t)r0 * SEQ + kc] == 0)     sc[ni][0] = -1e9f;
                if (mask[(size_t)r0 * SEQ + kc + 1] == 0) sc[ni][1] = -1e9f;
                if (mask[(size_t)r1 * SEQ + kc] == 0)     sc[ni][2] = -1e9f;
                if (mask[(size_t)r1 * SEQ + kc + 1] == 0) sc[ni][3] = -1e9f;
            }
        }

        float mxA = -1e30f, mxB = -1e30f;
        #pragma unroll
        for (int ni = 0; ni < 8; ni++) {
            mxA = fmaxf(mxA, fmaxf(sc[ni][0], sc[ni][1]));
            mxB = fmaxf(mxB, fmaxf(sc[ni][2], sc[ni][3]));
        }
        mxA = fmaxf(mxA, __shfl_xor_sync(0xffffffffu, mxA, 1));
        mxA = fmaxf(mxA, __shfl_xor_sync(0xffffffffu, mxA, 2));
        mxB = fmaxf(mxB, __shfl_xor_sync(0xffffffffu, mxB, 1));
        mxB = fmaxf(mxB, __shfl_xor_sync(0xffffffffu, mxB, 2));
        float mAn = fmaxf(mA, mxA), mBn = fmaxf(mB, mxB);
        float aA = __expf(mA - mAn), aB = __expf(mB - mBn);
        float sA = 0.f, sB = 0.f;
        #pragma unroll
        for (int ni = 0; ni < 8; ni++) {
            sc[ni][0] = __expf(sc[ni][0] - mAn); sA += sc[ni][0];
            sc[ni][1] = __expf(sc[ni][1] - mAn); sA += sc[ni][1];
            sc[ni][2] = __expf(sc[ni][2] - mBn); sB += sc[ni][2];
            sc[ni][3] = __expf(sc[ni][3] - mBn); sB += sc[ni][3];
        }
        sA += __shfl_xor_sync(0xffffffffu, sA, 1);
        sA += __shfl_xor_sync(0xffffffffu, sA, 2);
        sB += __shfl_xor_sync(0xffffffffu, sB, 1);
        sB += __shfl_xor_sync(0xffffffffu, sB, 2);
        lA = lA * aA + sA;
        lB = lB * aB + sB;
        mA = mAn; mB = mBn;
        #pragma unroll
        for (int ni = 0; ni < 16; ni++) {
            o[ni][0] *= aA; o[ni][1] *= aA;
            o[ni][2] *= aB; o[ni][3] *= aB;
        }

        uint32_t pa[4][4];
        #pragma unroll
        for (int jj = 0; jj < 4; jj++) {
            float* e0 = sc[2 * jj];
            float* e1 = sc[2 * jj + 1];
            pa[jj][0] = pack_h2(e0[0], e0[1]);
            pa[jj][1] = pack_h2(e0[2], e0[3]);
            pa[jj][2] = pack_h2(e1[0], e1[1]);
            pa[jj][3] = pack_h2(e1[2], e1[3]);
        }

        #pragma unroll
        for (int k16 = 0; k16 < 4; k16++) {
            #pragma unroll
            for (int n16 = 0; n16 < 8; n16++) {
                uint32_t vb4[4];
                LDSM_X4T(vb4, vbase + (uint32_t)(k16 * 16 + frow) * AKV_ROWB
                                    + (uint32_t)(n16 * 2 + hi) * 16);
                mma16(o[n16 * 2],     pa[k16], vb4[0], vb4[1]);
                mma16(o[n16 * 2 + 1], pa[k16], vb4[2], vb4[3]);
            }
        }

        __syncthreads();
        if (j + 2 < 32) {
            int row = tid >> 1, c16b = (tid & 1) * 8;
            uint32_t kd = smb + AKV_MATB + (uint32_t)buf * (2 * AKV_MATB);
            const __half* ks = Kg + (size_t)((j + 2) * 64 + row) * DKH;
            const __half* vs = Vg + (size_t)((j + 2) * 64 + row) * DKH;
            #pragma unroll
            for (int t = 0; t < 8; t++) {
                CP16(kd + (uint32_t)row * AKV_ROWB + (uint32_t)(c16b + t) * 16,
                     ks + (c16b + t) * 8);
                CP16(kd + AKV_MATB + (uint32_t)row * AKV_ROWB + (uint32_t)(c16b + t) * 16,
                     vs + (c16b + t) * 8);
            }
            CP_COMMIT();
        }
    }

    float rA = 1.f / lA, rB = 1.f / lB;
    int tok0 = b * SEQ + q0 + g, tok1 = tok0 + 8;
    #pragma unroll
    for (int ni = 0; ni < 16; ni++) {
        int d = ni * 8 + tq * 2;
        __half* p0 = ctx + (size_t)tok0 * DMODEL + h * DKH + d;
        __half* p1 = ctx + (size_t)tok1 * DMODEL + h * DKH + d;
        *(__half2*)p0 = __floats2half2_rn(o[ni][0] * rA, o[ni][1] * rA);
        *(__half2*)p1 = __floats2half2_rn(o[ni][2] * rB, o[ni][3] * rB);
    }
}

// ---------------- launch ----------------
extern "C" void kernel_launch(void* const* d_in, const int* in_sizes, int n_in,
                              void* d_out, int out_size) {
    const float* x     = (const float*)d_in[0];
    const int*   mask  = (const int*)d_in[1];
    const float* w_qkv = (const float*)d_in[2];
    const float* w_o   = (const float*)d_in[3];
    const float* ga1   = (const float*)d_in[4];
    const float* be1   = (const float*)d_in[5];
    const float* ga2   = (const float*)d_in[6];
    const float* be2   = (const float*)d_in[7];
    const float* w1    = (const float*)d_in[8];
    const float* b1    = (const float*)d_in[9];
    const float* w2    = (const float*)d_in[10];
    const float* b2    = (const float*)d_in[11];
    const float* ls    = (const float*)d_in[12];
    float* out = (float*)d_out;

    __half *ln1, *ln2, *q, *k, *v, *ctx, *hbuf, *wqkvb, *wob, *w1b, *w2b;
    int* flag;
    cudaGetSymbolAddress((void**)&ln1,   g_ln1);
    cudaGetSymbolAddress((void**)&ln2,   g_ln2);
    cudaGetSymbolAddress((void**)&q,     g_q);
    cudaGetSymbolAddress((void**)&k,     g_k);
    cudaGetSymbolAddress((void**)&v,     g_v);
    cudaGetSymbolAddress((void**)&ctx,   g_ctx);
    cudaGetSymbolAddress((void**)&hbuf,  g_h);
    cudaGetSymbolAddress((void**)&wqkvb, g_wqkv);
    cudaGetSymbolAddress((void**)&wob,   g_wo);
    cudaGetSymbolAddress((void**)&w1b,   g_w1);
    cudaGetSymbolAddress((void**)&w2b,   g_w2);
    cudaGetSymbolAddress((void**)&flag,  g_flag);

    cudaFuncSetAttribute(attn_f16, cudaFuncAttributeMaxDynamicSharedMemorySize, ATTN_SMEM);
    cudaFuncSetAttribute(gemm_f16<0>, cudaFuncAttributeMaxDynamicSharedMemorySize, SMEM_GEMM);
    cudaFuncSetAttribute(gemm_f16<1>, cudaFuncAttributeMaxDynamicSharedMemorySize, SMEM_GEMM);
    cudaFuncSetAttribute(gemm_f16<2>, cudaFuncAttributeMaxDynamicSharedMemorySize, SMEM_GEMM);
    cudaFuncSetAttribute(gemm_f16<3>, cudaFuncAttributeMaxDynamicSharedMemorySize, SMEM_GEMM);

    // side stream + events (host resources only; created once)
    static cudaStream_t s2 = nullptr;
    static cudaEvent_t evF = nullptr, evA = nullptr, evL = nullptr, evC = nullptr, evB = nullptr;
    if (s2 == nullptr) {
        cudaStreamCreateWithFlags(&s2, cudaStreamNonBlocking);
        cudaEventCreateWithFlags(&evF, cudaEventDisableTiming);
        cudaEventCreateWithFlags(&evA, cudaEventDisableTiming);
        cudaEventCreateWithFlags(&evL, cudaEventDisableTiming);
        cudaEventCreateWithFlags(&evC, cudaEventDisableTiming);
        cudaEventCreateWithFlags(&evB, cudaEventDisableTiming);
    }

    // ---- legal capture fork: record on origin, side stream waits ----
    cudaEventRecord(evF, 0);
    cudaStreamWaitEvent(s2, evF, 0);

    // main: weight conversion; side: layernorm (overlapped)
    cvt_all<<<(CVT_N0 + CVT_N1 + 2 * CVT_N2) / 256, 256>>>(
        w_qkv, w_o, w1, w2, wqkvb, wob, w1b, w2b);
    cudaEventRecord(evA, 0);
    ln_kernel<<<TOKS, 256, 0, s2>>>(x, ga1, be1, ga2, be2, ln1, ln2);
    cudaEventRecord(evL, s2);

    // side: QKV projection (needs ln1 [same stream] + wqkvb [evA])
    cudaStreamWaitEvent(s2, evA, 0);
    Epi e1 = {nullptr, nullptr, nullptr, nullptr, q, k, v};
    gemm_f16<0><<<dim3(48, 32), 256, SMEM_GEMM, s2>>>(ln1, wqkvb, TOKS, 3 * DMODEL, DMODEL, e1);

    // main: FF1 (needs ln2 [evL] + w1b [same stream])
    cudaStreamWaitEvent(0, evL, 0);
    Epi e3 = {b1, nullptr, nullptr, nullptr, hbuf, nullptr, nullptr};
    gemm_f16<2><<<dim3(64, 32), 256, SMEM_GEMM>>>(ln2, w1b, TOKS, DFF, DMODEL, e3);

    // main: mask flag
    flag_init<<<1, 32>>>(flag);
    mask_reduce<<<256, 256>>>(mask, in_sizes[1], flag);
    cudaEventRecord(evC, 0);

    // side: attention (needs QKV [same stream] + mask flag [evC])
    cudaStreamWaitEvent(s2, evC, 0);
    attn_f16<<<dim3(32, 32), 128, ATTN_SMEM, s2>>>(q, k, v, mask, flag, ctx);
    cudaEventRecord(evB, s2);

    // main: FF2 initializes out = x + ls*(h@w2 + b2)
    Epi e4 = {b2, ls, x, out, nullptr, nullptr, nullptr};
    gemm_f16<3><<<dim3(16, 32), 256, SMEM_GEMM>>>(hbuf, w2b, TOKS, DMODEL, DFF, e4);

    // join, then WO accumulates out += ctx @ w_o
    cudaStreamWaitEvent(0, evB, 0);
    Epi e2 = {nullptr, nullptr, nullptr, out, nullptr, nullptr, nullptr};
    gemm_f16<1><<<dim3(16, 32), 256, SMEM_GEMM>>>(ctx, wob, TOKS, DMODEL, DMODEL, e2);
}

// round 14
// speedup vs baseline: 1.2301x; 1.0607x over previous
#include <cuda_runtime.h>
#include <cuda_fp16.h>
#include <cstdint>
#include <cmath>

// ---------------- problem constants ----------------
#define TOKS 4096
#define DMODEL 2048
#define DFF 8192
#define NHEADS 16
#define DKH 128
#define SEQ 2048
#define BATCH 2

// ---------------- scratch (device globals) ----------------
__device__ __align__(128) __half g_ln1[TOKS * DMODEL];
__device__ __align__(128) __half g_ln2[TOKS * DMODEL];
__device__ __align__(128) __half g_q[TOKS * DMODEL];
__device__ __align__(128) __half g_k[TOKS * DMODEL];
__device__ __align__(128) __half g_v[TOKS * DMODEL];
__device__ __align__(128) __half g_ctx[TOKS * DMODEL];
__device__ __align__(128) __half g_h[TOKS * DFF];
__device__ __align__(128) __half g_wqkv[DMODEL * 3 * DMODEL];
__device__ __align__(128) __half g_wo[DMODEL * DMODEL];
__device__ __align__(128) __half g_w1[DMODEL * DFF];
__device__ __align__(128) __half g_w2[DFF * DMODEL];
__device__ int g_flag[1];

// ---------------- helpers ----------------
__device__ __forceinline__ uint32_t smem_u32(const void* p) {
    uint32_t a;
    asm("{ .reg .u64 t; cvta.to.shared.u64 t, %1; cvt.u32.u64 %0, t; }"
        : "=r"(a) : "l"(p));
    return a;
}

#define CP16(dst, src) \
    asm volatile("cp.async.cg.shared.global [%0], [%1], 16;" \
                 :: "r"(dst), "l"(src) : "memory")
#define CP_COMMIT() asm volatile("cp.async.commit_group;" ::: "memory")
#define CP_WAIT1()  asm volatile("cp.async.wait_group 1;" ::: "memory")

#define LDSM_X4(r, addr) \
    asm volatile("ldmatrix.sync.aligned.m8n8.x4.shared.b16 {%0,%1,%2,%3}, [%4];" \
        : "=r"((r)[0]), "=r"((r)[1]), "=r"((r)[2]), "=r"((r)[3]) : "r"(addr))
#define LDSM_X4T(r, addr) \
    asm volatile("ldmatrix.sync.aligned.m8n8.x4.trans.shared.b16 {%0,%1,%2,%3}, [%4];" \
        : "=r"((r)[0]), "=r"((r)[1]), "=r"((r)[2]), "=r"((r)[3]) : "r"(addr))

__device__ __forceinline__ void mma16(float* c, const uint32_t* a, uint32_t b0, uint32_t b1) {
    asm volatile(
        "mma.sync.aligned.m16n8k16.row.col.f32.f16.f16.f32 "
        "{%0,%1,%2,%3},{%4,%5,%6,%7},{%8,%9},{%0,%1,%2,%3};"
        : "+f"(c[0]), "+f"(c[1]), "+f"(c[2]), "+f"(c[3])
        : "r"(a[0]), "r"(a[1]), "r"(a[2]), "r"(a[3]), "r"(b0), "r"(b1));
}

__device__ __forceinline__ uint32_t pack_h2(float x, float y) {
    __half2 t = __floats2half2_rn(x, y);
    return *(uint32_t*)&t;
}

// ---------------- fp32 -> fp16 converter (all 4 weights, one launch) ----------------
#define CVT_N0 (DMODEL * 3 * DMODEL / 4)
#define CVT_N1 (DMODEL * DMODEL / 4)
#define CVT_N2 (DMODEL * DFF / 4)
__global__ void cvt_all(const float* __restrict__ wqkv, const float* __restrict__ wo,
                        const float* __restrict__ w1, const float* __restrict__ w2,
                        __half* __restrict__ oqkv, __half* __restrict__ owo,
                        __half* __restrict__ ow1, __half* __restrict__ ow2) {
    int idx = blockIdx.x * blockDim.x + threadIdx.x;
    const float* in;
    __half* out;
    int off;
    if (idx < CVT_N0)                          { in = wqkv; out = oqkv; off = idx; }
    else if (idx < CVT_N0 + CVT_N1)            { in = wo;   out = owo;  off = idx - CVT_N0; }
    else if (idx < CVT_N0 + CVT_N1 + CVT_N2)   { in = w1;   out = ow1;  off = idx - CVT_N0 - CVT_N1; }
    else                                       { in = w2;   out = ow2;  off = idx - CVT_N0 - CVT_N1 - CVT_N2; }
    float4 v = ((const float4*)in)[off];
    ((__half2*)out)[off * 2]     = __floats2half2_rn(v.x, v.y);
    ((__half2*)out)[off * 2 + 1] = __floats2half2_rn(v.z, v.w);
}

// ---------------- LayerNorm: fp32 x -> fp16 ln1, ln2 ----------------
__global__ void ln_kernel(const float* __restrict__ x,
                          const float* __restrict__ ga1, const float* __restrict__ be1,
                          const float* __restrict__ ga2, const float* __restrict__ be2,
                          __half* __restrict__ o1, __half* __restrict__ o2) {
    int t = blockIdx.x;
    int tid = threadIdx.x;
    const float4* xr = (const float4*)(x + (size_t)t * DMODEL);
    float4 a = xr[tid];
    float4 bq = xr[tid + 256];
    float s  = a.x + a.y + a.z + a.w + bq.x + bq.y + bq.z + bq.w;
    float s2 = a.x*a.x + a.y*a.y + a.z*a.z + a.w*a.w +
               bq.x*bq.x + bq.y*bq.y + bq.z*bq.z + bq.w*bq.w;
    #pragma unroll
    for (int o = 16; o; o >>= 1) {
        s  += __shfl_xor_sync(0xffffffffu, s,  o);
        s2 += __shfl_xor_sync(0xffffffffu, s2, o);
    }
    __shared__ float rs[8], rs2[8], stats[2];
    if ((tid & 31) == 0) { rs[tid >> 5] = s; rs2[tid >> 5] = s2; }
    __syncthreads();
    if (tid == 0) {
        float S = 0.f, S2 = 0.f;
        for (int i = 0; i < 8; i++) { S += rs[i]; S2 += rs2[i]; }
        float mu = S * (1.0f / DMODEL);
        float var = S2 * (1.0f / DMODEL) - mu * mu;
        stats[0] = mu;
        stats[1] = rsqrtf(var + 1e-5f);
    }
    __syncthreads();
    float mu = stats[0], r = stats[1];
    const float4* G1 = (const float4*)ga1;
    const float4* B1 = (const float4*)be1;
    const float4* G2 = (const float4*)ga2;
    const float4* B2 = (const float4*)be2;
    __half2* O1 = (__half2*)(o1 + (size_t)t * DMODEL);
    __half2* O2 = (__half2*)(o2 + (size_t)t * DMODEL);
    #pragma unroll
    for (int i = 0; i < 2; i++) {
        int idx = tid + i * 256;
        float4 v = (i == 0) ? a : bq;
        float nx = (v.x - mu) * r, ny = (v.y - mu) * r, nz = (v.z - mu) * r, nw = (v.w - mu) * r;
        float4 g1v = G1[idx], b1v = B1[idx], g2v = G2[idx], b2v = B2[idx];
        O1[idx * 2]     = __floats2half2_rn(nx * g1v.x + b1v.x, ny * g1v.y + b1v.y);
        O1[idx * 2 + 1] = __floats2half2_rn(nz * g1v.z + b1v.z, nw * g1v.w + b1v.w);
        O2[idx * 2]     = __floats2half2_rn(nx * g2v.x + b2v.x, ny * g2v.y + b2v.y);
        O2[idx * 2 + 1] = __floats2half2_rn(nz * g2v.z + b2v.z, nw * g2v.w + b2v.w);
    }
}

// ---------------- mask flag ----------------
__global__ void flag_init(int* flag) { if (threadIdx.x == 0) flag[0] = 1; }

__global__ void mask_reduce(const int* __restrict__ mask, int n, int* __restrict__ flag) {
    bool bad = false;
    for (int i = blockIdx.x * blockDim.x + threadIdx.x; i < n; i += gridDim.x * blockDim.x)
        if (mask[i] == 0) bad = true;
    if (bad) flag[0] = 0;
}

// ======== fp16 GEMM: 128x128 tile, K-chunk 64, 3 stages, 256 threads, 2 CTAs/SM ========
#define A_ROWB  144
#define A_BYTES (128 * A_ROWB)
#define B_ROWB  272
#define B_BYTES (64 * B_ROWB)
#define STAGE   (A_BYTES + B_BYTES)
#define NSTAGE  3
#define SMEM_GEMM (STAGE * NSTAGE)

struct Epi {
    const float* c0;
    const float* c1;
    const float* c2;
    float* o0;
    __half* bo0;
    __half* bo1;
    __half* bo2;
};

template <int E>
__device__ __forceinline__ void emit2(int r, int c, int N, float v0, float v1, const Epi& e) {
    if (E == 0) {
        int which = c >> 11, hh = (c >> 7) & 15, d0 = c & 127;
        __half* dst = (which == 0) ? e.bo0 : ((which == 1) ? e.bo1 : e.bo2);
        int b = r >> 11, s = r & 2047;
        __half* p = dst + (size_t)((b << 4) + hh) * (SEQ * DKH) + (size_t)s * DKH + d0;
        *(__half2*)p = __floats2half2_rn(v0, v1);
    } else if (E == 1) {
        size_t i = (size_t)r * N + c;
        float2 o = *(const float2*)(e.o0 + i);
        o.x += v0;
        o.y += v1;
        *(float2*)(e.o0 + i) = o;
    } else if (E == 2) {
        const float is2 = 0.70710678118654752f;
        float t0 = v0 + e.c0[c], t1 = v1 + e.c0[c + 1];
        float g0 = 0.5f * t0 * (1.0f + erff(t0 * is2));
        float g1 = 0.5f * t1 * (1.0f + erff(t1 * is2));
        __half* p = e.bo0 + (size_t)r * N + c;
        *(__half2*)p = __floats2half2_rn(g0, g1);
    } else {
        size_t i = (size_t)r * N + c;
        float2 xv = *(const float2*)(e.c2 + i);
        float2 bb = *(const float2*)(e.c0 + c);
        float2 ls = *(const float2*)(e.c1 + c);
        float2 o;
        o.x = xv.x + ls.x * (v0 + bb.x);
        o.y = xv.y + ls.y * (v1 + bb.y);
        *(float2*)(e.o0 + i) = o;
    }
}

__device__ __forceinline__ void gemm_load_stage(const __half* A, const __half* B,
                                                int K, int N, int bm, int bn, int kt,
                                                uint32_t base, int tid) {
    #pragma unroll
    for (int t = 0; t < 4; t++) {
        int c = tid + t * 256;
        int row = c >> 3, k8 = c & 7;
        const __half* src = A + (size_t)(bm + row) * K + kt * 64 + k8 * 8;
        CP16(base + (uint32_t)row * A_ROWB + (uint32_t)k8 * 16, src);
    }
    #pragma unroll
    for (int t = 0; t < 4; t++) {
        int c = tid + t * 256;
        int row = c >> 4, n8 = c & 15;
        const __half* src = B + (size_t)(kt * 64 + row) * N + bn + n8 * 8;
        CP16(base + A_BYTES + (uint32_t)row * B_ROWB + (uint32_t)n8 * 16, src);
    }
    CP_COMMIT();
}

template <int E>
__global__ __launch_bounds__(256, 2)
void gemm_f16(const __half* __restrict__ A, const __half* __restrict__ B,
              int M, int N, int K, Epi e) {
    extern __shared__ __align__(128) char smc[];
    uint32_t smb = smem_u32(smc);
    int tid = threadIdx.x, warp = tid >> 5, lane = tid & 31;
    int bm = blockIdx.y * 128, bn = blockIdx.x * 128;
    int wm = (warp >> 1) * 32, wn = (warp & 1) * 64;
    const int nt = K >> 6;

    float acc[2][8][4];
    #pragma unroll
    for (int i = 0; i < 2; i++)
        #pragma unroll
        for (int j = 0; j < 8; j++)
            #pragma unroll
            for (int k = 0; k < 4; k++) acc[i][j][k] = 0.f;

    gemm_load_stage(A, B, K, N, bm, bn, 0, smb, tid);
    gemm_load_stage(A, B, K, N, bm, bn, 1, smb + STAGE, tid);

    int frow = (lane & 7) + ((lane >> 3) & 1) * 8;
    int hi = lane >> 4;

    for (int i = 0; i < nt; i++) {
        CP_WAIT1();
        __syncthreads();
        if (i + 2 < nt)
            gemm_load_stage(A, B, K, N, bm, bn, i + 2, smb + (uint32_t)((i + 2) % 3) * STAGE, tid);

        uint32_t abase = smb + (uint32_t)(i % 3) * STAGE;
        uint32_t bbase = abase + A_BYTES;
        #pragma unroll
        for (int k16 = 0; k16 < 4; k16++) {
            uint32_t a[2][4], bf[4][4];
            #pragma unroll
            for (int mt = 0; mt < 2; mt++) {
                uint32_t ad = abase + (uint32_t)(wm + mt * 16 + frow) * A_ROWB
                            + (uint32_t)(k16 * 2 + hi) * 16;
                LDSM_X4(a[mt], ad);
            }
            LDSM_X4T(bf[0], bbase + (uint32_t)(k16 * 16 + frow) * B_ROWB
                          + (uint32_t)((wn >> 3) + hi) * 16);
            #pragma unroll
            for (int nt16 = 0; nt16 < 4; nt16++) {
                if (nt16 < 3) {
                    LDSM_X4T(bf[nt16 + 1], bbase + (uint32_t)(k16 * 16 + frow) * B_ROWB
                                         + (uint32_t)(((wn + (nt16 + 1) * 16) >> 3) + hi) * 16);
                }
                #pragma unroll
                for (int mt = 0; mt < 2; mt++) {
                    mma16(acc[mt][nt16 * 2],     a[mt], bf[nt16][0], bf[nt16][1]);
                    mma16(acc[mt][nt16 * 2 + 1], a[mt], bf[nt16][2], bf[nt16][3]);
                }
            }
        }
    }

    int g = lane >> 2, tq = lane & 3;
    #pragma unroll
    for (int mt = 0; mt < 2; mt++) {
        int r0 = bm + wm + mt * 16 + g;
        #pragma unroll
        for (int n8 = 0; n8 < 8; n8++) {
            int c0 = bn + wn + n8 * 8 + tq * 2;
            emit2<E>(r0,     c0, N, acc[mt][n8][0], acc[mt][n8][1], e);
            emit2<E>(r0 + 8, c0, N, acc[mt][n8][2], acc[mt][n8][3], e);
        }
    }
}

// ======== flash attention: q-tile 128, 256 threads (8 warps), fp16 P in regs ========
#define AKV_ROWB 272
#define AKV_MATB 17408                    // 64 rows * 272B
#define AQ_BYTES (128 * AKV_ROWB)         // 34816
#define ATTN_SMEM (AQ_BYTES + 4 * AKV_MATB)   // 104448

__global__ __launch_bounds__(256)
void attn_f16(const __half* __restrict__ Q, const __half* __restrict__ K,
              const __half* __restrict__ V, const int* __restrict__ mask,
              const int* __restrict__ flag, __half* __restrict__ ctx) {
    extern __shared__ __align__(128) char sma[];
    uint32_t smb = smem_u32(sma);
    int tid = threadIdx.x, warp = tid >> 5, lane = tid & 31;
    int g = lane >> 2, tq = lane & 3;
    int frow = (lane & 7) + ((lane >> 3) & 1) * 8;
    int hi = lane >> 4;
    int qt = blockIdx.x, bh = blockIdx.y;
    int b = bh >> 4, h = bh & 15;
    const __half* Qg = Q + (size_t)bh * SEQ * DKH + (size_t)(qt * 128) * DKH;
    const __half* Kg = K + (size_t)bh * SEQ * DKH;
    const __half* Vg = V + (size_t)bh * SEQ * DKH;
    int q0 = qt * 128 + warp * 16;
    int allv = flag[0];

    // load Q (128 rows) + KV tile0, then KV tile1
    {
        int qrow = tid >> 1, qc8 = (tid & 1) * 8;   // 256 thr: 128 rows x 2 halves
        #pragma unroll
        for (int t = 0; t < 8; t++)
            CP16(smb + (uint32_t)qrow * AKV_ROWB + (uint32_t)(qc8 + t) * 16,
                 Qg + (size_t)qrow * DKH + (qc8 + t) * 8);
        int row = tid >> 2, c4 = (tid & 3) * 4;     // 256 thr: 64 rows x 4 quarters
        #pragma unroll
        for (int t = 0; t < 4; t++) {
            CP16(smb + AQ_BYTES + (uint32_t)row * AKV_ROWB + (uint32_t)(c4 + t) * 16,
                 Kg + (size_t)row * DKH + (c4 + t) * 8);
            CP16(smb + AQ_BYTES + AKV_MATB + (uint32_t)row * AKV_ROWB + (uint32_t)(c4 + t) * 16,
                 Vg + (size_t)row * DKH + (c4 + t) * 8);
        }
        CP_COMMIT();
        #pragma unroll
        for (int t = 0; t < 4; t++) {
            CP16(smb + AQ_BYTES + 2 * AKV_MATB + (uint32_t)row * AKV_ROWB + (uint32_t)(c4 + t) * 16,
                 Kg + (size_t)(64 + row) * DKH + (c4 + t) * 8);
            CP16(smb + AQ_BYTES + 3 * AKV_MATB + (uint32_t)row * AKV_ROWB + (uint32_t)(c4 + t) * 16,
                 Vg + (size_t)(64 + row) * DKH + (c4 + t) * 8);
        }
        CP_COMMIT();
    }

    CP_WAIT1();
    __syncthreads();

    uint32_t qa[8][4];
    #pragma unroll
    for (int k16 = 0; k16 < 8; k16++)
        LDSM_X4(qa[k16], smb + (uint32_t)(warp * 16 + frow) * AKV_ROWB
                             + (uint32_t)(k16 * 2 + hi) * 16);

    float o[16][4];
    #pragma unroll
    for (int i = 0; i < 16; i++)
        #pragma unroll
        for (int j = 0; j < 4; j++) o[i][j] = 0.f;
    float mA = -1e30f, mB = -1e30f, lA = 0.f, lB = 0.f;

    for (int j = 0; j < 32; j++) {
        if (j > 0) { CP_WAIT1(); __syncthreads(); }
        int buf = j & 1;
        uint32_t kbase = smb + AQ_BYTES + (uint32_t)buf * (2 * AKV_MATB);
        uint32_t vbase = kbase + AKV_MATB;

        float sc[8][4];
        #pragma unroll
        for (int ni = 0; ni < 8; ni++)
            #pragma unroll
            for (int c = 0; c < 4; c++) sc[ni][c] = 0.f;
        #pragma unroll
        for (int k16 = 0; k16 < 8; k16++) {
            #pragma unroll
            for (int n16 = 0; n16 < 4; n16++) {
                uint32_t kb[4];
                LDSM_X4(kb, kbase + (uint32_t)(n16 * 16 + frow) * AKV_ROWB
                                  + (uint32_t)(k16 * 2 + hi) * 16);
                mma16(sc[n16 * 2],     qa[k16], kb[0], kb[2]);
                mma16(sc[n16 * 2 + 1], qa[k16], kb[1], kb[3]);
            }
        }
        const float sscale = 0.0883883476483184f;
        #pragma unroll
        for (int ni = 0; ni < 8; ni++)
            #pragma unroll
            for (int c = 0; c < 4; c++) sc[ni][c] *= sscale;

        if (!allv) {
            #pragma unroll
            for (int ni = 0; ni < 8; ni++) {
                int kc = j * 64 + ni * 8 + tq * 2;
                int r0 = q0 + g, r1 = q0 + g + 8;
                if (mask[(size_t)r0 * SEQ + kc] == 0)     sc[ni][0] = -1e9f;
                if (mask[(size_t)r0 * SEQ + kc + 1] == 0) sc[ni][1] = -1e9f;
                if (mask[(size_t)r1 * SEQ + kc] == 0)     sc[ni][2] = -1e9f;
                if (mask[(size_t)r1 * SEQ + kc + 1] == 0) sc[ni][3] = -1e9f;
            }
        }

        float mxA = -1e30f, mxB = -1e30f;
        #pragma unroll
        for (int ni = 0; ni < 8; ni++) {
            mxA = fmaxf(mxA, fmaxf(sc[ni][0], sc[ni][1]));
            mxB = fmaxf(mxB, fmaxf(sc[ni][2], sc[ni][3]));
        }
        mxA = fmaxf(mxA, __shfl_xor_sync(0xffffffffu, mxA, 1));
        mxA = fmaxf(mxA, __shfl_xor_sync(0xffffffffu, mxA, 2));
        mxB = fmaxf(mxB, __shfl_xor_sync(0xffffffffu, mxB, 1));
        mxB = fmaxf(mxB, __shfl_xor_sync(0xffffffffu, mxB, 2));
        float mAn = fmaxf(mA, mxA), mBn = fmaxf(mB, mxB);
        float aA = __expf(mA - mAn), aB = __expf(mB - mBn);
        float sA = 0.f, sB = 0.f;
        #pragma unroll
        for (int ni = 0; ni < 8; ni++) {
            sc[ni][0] = __expf(sc[ni][0] - mAn); sA += sc[ni][0];
            sc[ni][1] = __expf(sc[ni][1] - mAn); sA += sc[ni][1];
            sc[ni][2] = __expf(sc[ni][2] - mBn); sB += sc[ni][2];
            sc[ni][3] = __expf(sc[ni][3] - mBn); sB += sc[ni][3];
        }
        sA += __shfl_xor_sync(0xffffffffu, sA, 1);
        sA += __shfl_xor_sync(0xffffffffu, sA, 2);
        sB += __shfl_xor_sync(0xffffffffu, sB, 1);
        sB += __shfl_xor_sync(0xffffffffu, sB, 2);
        lA = lA * aA + sA;
        lB = lB * aB + sB;
        mA = mAn; mB = mBn;
        #pragma unroll
        for (int ni = 0; ni < 16; ni++) {
            o[ni][0] *= aA; o[ni][1] *= aA;
            o[ni][2] *= aB; o[ni][3] *= aB;
        }

        uint32_t pa[4][4];
        #pragma unroll
        for (int jj = 0; jj < 4; jj++) {
            float* e0 = sc[2 * jj];
            float* e1 = sc[2 * jj + 1];
            pa[jj][0] = pack_h2(e0[0], e0[1]);
            pa[jj][1] = pack_h2(e0[2], e0[3]);
            pa[jj][2] = pack_h2(e1[0], e1[1]);
            pa[jj][3] = pack_h2(e1[2], e1[3]);
        }

        #pragma unroll
        for (int k16 = 0; k16 < 4; k16++) {
            #pragma unroll
            for (int n16 = 0; n16 < 8; n16++) {
                uint32_t vb4[4];
                LDSM_X4T(vb4, vbase + (uint32_t)(k16 * 16 + frow) * AKV_ROWB
                                    + (uint32_t)(n16 * 2 + hi) * 16);
                mma16(o[n16 * 2],     pa[k16], vb4[0], vb4[1]);
                mma16(o[n16 * 2 + 1], pa[k16], vb4[2], vb4[3]);
            }
        }

        __syncthreads();
        if (j + 2 < 32) {
            int row = tid >> 2, c4 = (tid & 3) * 4;
            uint32_t kd = smb + AQ_BYTES + (uint32_t)buf * (2 * AKV_MATB);
            const __half* ks = Kg + (size_t)((j + 2) * 64 + row) * DKH;
            const __half* vs = Vg + (size_t)((j + 2) * 64 + row) * DKH;
            #pragma unroll
            for (int t = 0; t < 4; t++) {
                CP16(kd + (uint32_t)row * AKV_ROWB + (uint32_t)(c4 + t) * 16,
                     ks + (c4 + t) * 8);
                CP16(kd + AKV_MATB + (uint32_t)row * AKV_ROWB + (uint32_t)(c4 + t) * 16,
                     vs + (c4 + t) * 8);
            }
            CP_COMMIT();
        }
    }

    float rA = 1.f / lA, rB = 1.f / lB;
    int tok0 = b * SEQ + q0 + g, tok1 = tok0 + 8;
    #pragma unroll
    for (int ni = 0; ni < 16; ni++) {
        int d = ni * 8 + tq * 2;
        __half* p0 = ctx + (size_t)tok0 * DMODEL + h * DKH + d;
        __half* p1 = ctx + (size_t)tok1 * DMODEL + h * DKH + d;
        *(__half2*)p0 = __floats2half2_rn(o[ni][0] * rA, o[ni][1] * rA);
        *(__half2*)p1 = __floats2half2_rn(o[ni][2] * rB, o[ni][3] * rB);
    }
}

// ---------------- launch ----------------
extern "C" void kernel_launch(void* const* d_in, const int* in_sizes, int n_in,
                              void* d_out, int out_size) {
    const float* x     = (const float*)d_in[0];
    const int*   mask  = (const int*)d_in[1];
    const float* w_qkv = (const float*)d_in[2];
    const float* w_o   = (const float*)d_in[3];
    const float* ga1   = (const float*)d_in[4];
    const float* be1   = (const float*)d_in[5];
    const float* ga2   = (const float*)d_in[6];
    const float* be2   = (const float*)d_in[7];
    const float* w1    = (const float*)d_in[8];
    const float* b1    = (const float*)d_in[9];
    const float* w2    = (const float*)d_in[10];
    const float* b2    = (const float*)d_in[11];
    const float* ls    = (const float*)d_in[12];
    float* out = (float*)d_out;

    __half *ln1, *ln2, *q, *k, *v, *ctx, *hbuf, *wqkvb, *wob, *w1b, *w2b;
    int* flag;
    cudaGetSymbolAddress((void**)&ln1,   g_ln1);
    cudaGetSymbolAddress((void**)&ln2,   g_ln2);
    cudaGetSymbolAddress((void**)&q,     g_q);
    cudaGetSymbolAddress((void**)&k,     g_k);
    cudaGetSymbolAddress((void**)&v,     g_v);
    cudaGetSymbolAddress((void**)&ctx,   g_ctx);
    cudaGetSymbolAddress((void**)&hbuf,  g_h);
    cudaGetSymbolAddress((void**)&wqkvb, g_wqkv);
    cudaGetSymbolAddress((void**)&wob,   g_wo);
    cudaGetSymbolAddress((void**)&w1b,   g_w1);
    cudaGetSymbolAddress((void**)&w2b,   g_w2);
    cudaGetSymbolAddress((void**)&flag,  g_flag);

    cudaFuncSetAttribute(attn_f16, cudaFuncAttributeMaxDynamicSharedMemorySize, ATTN_SMEM);
    cudaFuncSetAttribute(gemm_f16<0>, cudaFuncAttributeMaxDynamicSharedMemorySize, SMEM_GEMM);
    cudaFuncSetAttribute(gemm_f16<1>, cudaFuncAttributeMaxDynamicSharedMemorySize, SMEM_GEMM);
    cudaFuncSetAttribute(gemm_f16<2>, cudaFuncAttributeMaxDynamicSharedMemorySize, SMEM_GEMM);
    cudaFuncSetAttribute(gemm_f16<3>, cudaFuncAttributeMaxDynamicSharedMemorySize, SMEM_GEMM);

    // side stream + events (host resources only; created once)
    static cudaStream_t s2 = nullptr;
    static cudaEvent_t evF = nullptr, evA = nullptr, evL = nullptr, evC = nullptr, evB = nullptr;
    if (s2 == nullptr) {
        cudaStreamCreateWithFlags(&s2, cudaStreamNonBlocking);
        cudaEventCreateWithFlags(&evF, cudaEventDisableTiming);
        cudaEventCreateWithFlags(&evA, cudaEventDisableTiming);
        cudaEventCreateWithFlags(&evL, cudaEventDisableTiming);
        cudaEventCreateWithFlags(&evC, cudaEventDisableTiming);
        cudaEventCreateWithFlags(&evB, cudaEventDisableTiming);
    }

    // legal capture fork: record on origin, side stream waits
    cudaEventRecord(evF, 0);
    cudaStreamWaitEvent(s2, evF, 0);

    // main: weight conversion; side: layernorm (overlapped)
    cvt_all<<<(CVT_N0 + CVT_N1 + 2 * CVT_N2) / 256, 256>>>(
        w_qkv, w_o, w1, w2, wqkvb, wob, w1b, w2b);
    cudaEventRecord(evA, 0);
    ln_kernel<<<TOKS, 256, 0, s2>>>(x, ga1, be1, ga2, be2, ln1, ln2);
    cudaEventRecord(evL, s2);

    // side: QKV projection (needs ln1 [same stream] + wqkvb [evA])
    cudaStreamWaitEvent(s2, evA, 0);
    Epi e1 = {nullptr, nullptr, nullptr, nullptr, q, k, v};
    gemm_f16<0><<<dim3(48, 32), 256, SMEM_GEMM, s2>>>(ln1, wqkvb, TOKS, 3 * DMODEL, DMODEL, e1);

    // main: FF1 (needs ln2 [evL] + w1b [same stream])
    cudaStreamWaitEvent(0, evL, 0);
    Epi e3 = {b1, nullptr, nullptr, nullptr, hbuf, nullptr, nullptr};
    gemm_f16<2><<<dim3(64, 32), 256, SMEM_GEMM>>>(ln2, w1b, TOKS, DFF, DMODEL, e3);

    // main: mask flag
    flag_init<<<1, 32>>>(flag);
    mask_reduce<<<256, 256>>>(mask, in_sizes[1], flag);
    cudaEventRecord(evC, 0);

    // side: attention (needs QKV [same stream] + mask flag [evC])
    cudaStreamWaitEvent(s2, evC, 0);
    attn_f16<<<dim3(16, 32), 256, ATTN_SMEM, s2>>>(q, k, v, mask, flag, ctx);
    cudaEventRecord(evB, s2);

    // main: FF2 initializes out = x + ls*(h@w2 + b2)
    Epi e4 = {b2, ls, x, out, nullptr, nullptr, nullptr};
    gemm_f16<3><<<dim3(16, 32), 256, SMEM_GEMM>>>(hbuf, w2b, TOKS, DMODEL, DFF, e4);

    // join, then WO accumulates out += ctx @ w_o
    cudaStreamWaitEvent(0, evB, 0);
    Epi e2 = {nullptr, nullptr, nullptr, out, nullptr, nullptr, nullptr};
    gemm_f16<1><<<dim3(16, 32), 256, SMEM_GEMM>>>(ctx, wob, TOKS, DMODEL, DMODEL, e2);
}